// round 10
// baseline (speedup 1.0000x reference)
#include <cuda_runtime.h>
#include <cuda_fp16.h>
#include <math.h>
#include <stdint.h>

#define NTOK   8192      // B*T
#define DM     1024
#define DFF    4096
#define TSEQ   2048
#define NH     16
#define DH     64

// ---------------- scratch (static device globals; no allocation) ----------------
__device__ __half g_h  [NTOK * DM];       // LN output (fp16)
__device__ __half g_qkv[NTOK * 3 * DM];   // qkv projections (fp16)
__device__ __half g_o  [NTOK * DM];       // attention output (fp16)
__device__ float  g_x2 [NTOK * DM];       // residual after attention (fp32)
__device__ __half g_ff [NTOK * DFF];      // gelu output (fp16)
__device__ __half g_wc [DM*3*DM + DM*DM + DM*DFF + DFF*DM]; // fp16 weights, [n][k]

// ---------------- weight transpose + fp16 convert: out[n][k] = h(in[k][n]) ----
__global__ void __launch_bounds__(256) transpose_h_kernel(
    const float* __restrict__ in, __half* __restrict__ out, int K, int N)
{
    __shared__ float tile[32][33];
    const int n0 = blockIdx.x * 32, k0 = blockIdx.y * 32;
    const int tx = threadIdx.x, ty = threadIdx.y;   // block (32, 8)
#pragma unroll
    for (int i = 0; i < 4; i++)
        tile[ty + i * 8][tx] = in[(size_t)(k0 + ty + i * 8) * N + n0 + tx];
    __syncthreads();
#pragma unroll
    for (int i = 0; i < 4; i++)
        out[(size_t)(n0 + ty + i * 8) * K + k0 + tx] =
            __float2half_rn(tile[tx][ty + i * 8]);
}

// ---------------- LayerNorm: fp32 in -> fp16 out ----------------
__global__ void __launch_bounds__(256) ln_kernel(
    const float* __restrict__ x, const float* __restrict__ g,
    const float* __restrict__ b, __half* __restrict__ out)
{
    const int row = blockIdx.x;
    const float* xr = x + (size_t)row * DM;
    float v[4];
    float s = 0.f, s2 = 0.f;
#pragma unroll
    for (int i = 0; i < 4; i++) {
        v[i] = xr[threadIdx.x + i * 256];
        s += v[i]; s2 += v[i] * v[i];
    }
#pragma unroll
    for (int off = 16; off; off >>= 1) {
        s  += __shfl_xor_sync(0xffffffffu, s,  off);
        s2 += __shfl_xor_sync(0xffffffffu, s2, off);
    }
    __shared__ float ss[8], ss2[8];
    const int w = threadIdx.x >> 5, ln = threadIdx.x & 31;
    if (ln == 0) { ss[w] = s; ss2[w] = s2; }
    __syncthreads();
    s = 0.f; s2 = 0.f;
#pragma unroll
    for (int i = 0; i < 8; i++) { s += ss[i]; s2 += ss2[i]; }
    const float mean = s * (1.0f / DM);
    const float var  = s2 * (1.0f / DM) - mean * mean;
    const float rstd = rsqrtf(var + 1e-5f);
    __half* orow = out + (size_t)row * DM;
#pragma unroll
    for (int i = 0; i < 4; i++) {
        const int c = threadIdx.x + i * 256;
        orow[c] = __float2half_rn((v[i] - mean) * rstd * g[c] + b[c]);
    }
}

// ================ fp16 tensor-core GEMM (f32 accumulate) ================
// C[M,N] = A[M,K] @ W[K,N]; Bt = W^T as [n][k] half rows.
// 128x128 tile, BK=32, 256 threads, 4-stage cp.async, ONE barrier per K-step.
// EPI: 0 plain half out, 1 bias+GELU half out, 2 bias+residual float out.
__device__ __forceinline__ float gelu_exact(float x) {
    return 0.5f * x * (1.0f + erff(x * 0.70710678118654752f));
}
__device__ __forceinline__ void ldsm4(uint32_t& r0, uint32_t& r1,
                                      uint32_t& r2, uint32_t& r3, uint32_t addr) {
    asm volatile("ldmatrix.sync.aligned.m8n8.x4.shared.b16 {%0,%1,%2,%3}, [%4];\n"
                 : "=r"(r0), "=r"(r1), "=r"(r2), "=r"(r3) : "r"(addr));
}
__device__ __forceinline__ void ldsm4t(uint32_t& r0, uint32_t& r1,
                                       uint32_t& r2, uint32_t& r3, uint32_t addr) {
    asm volatile("ldmatrix.sync.aligned.m8n8.x4.trans.shared.b16 {%0,%1,%2,%3}, [%4];\n"
                 : "=r"(r0), "=r"(r1), "=r"(r2), "=r"(r3) : "r"(addr));
}
__device__ __forceinline__ void mma_f16(float* c,
    uint32_t a0, uint32_t a1, uint32_t a2, uint32_t a3, uint32_t b0, uint32_t b1) {
    asm volatile(
        "mma.sync.aligned.m16n8k16.row.col.f32.f16.f16.f32 "
        "{%0,%1,%2,%3}, {%4,%5,%6,%7}, {%8,%9}, {%0,%1,%2,%3};\n"
        : "+f"(c[0]), "+f"(c[1]), "+f"(c[2]), "+f"(c[3])
        : "r"(a0), "r"(a1), "r"(a2), "r"(a3), "r"(b0), "r"(b1));
}
__device__ __forceinline__ void cp16(__half* dst, const __half* src) {
    uint32_t d = (uint32_t)__cvta_generic_to_shared(dst);
    asm volatile("cp.async.cg.shared.global [%0], [%1], 16;\n" :: "r"(d), "l"(src));
}

#define GPITCH 40                       // halves per smem row (64B data + 16B pad)
#define G_TILE (128 * GPITCH)           // halves per operand tile
#define G_STAGE (2 * G_TILE)            // halves per stage (A + B)
#define GEMM_SMEM (4 * G_STAGE * 2)     // bytes (= 81920), 4 stages

template<int EPI>
__global__ void __launch_bounds__(256) gemm_f16(
    const __half* __restrict__ A, const __half* __restrict__ Bt,
    const float* __restrict__ bias, const float* __restrict__ res,
    float* __restrict__ Cf, __half* __restrict__ Ch, int M, int N, int K)
{
    extern __shared__ __half smh[];
    const int tid  = threadIdx.x;
    const int lane = tid & 31, wid = tid >> 5;
    const int bm = blockIdx.y * 128, bn = blockIdx.x * 128;
    const int wm = (wid >> 2) * 64;
    const int wn = (wid & 3) * 32;
    const int gr = lane >> 2, tg = lane & 3;

    const uint32_t smem_u32 = (uint32_t)__cvta_generic_to_shared(smh);
    const int mat  = lane >> 3;         // ldmatrix matrix id 0..3
    const int mrow = lane & 7;

    float acc[4][4][4];
#pragma unroll
    for (int i = 0; i < 4; i++)
#pragma unroll
        for (int j = 0; j < 4; j++)
#pragma unroll
            for (int r = 0; r < 4; r++) acc[i][j][r] = 0.f;

    const int KT = K >> 5;

    auto issue = [&](int kt) {
        const int stg = kt & 3;
        const int k0 = kt << 5;
        __half* As = smh + stg * G_STAGE;
        __half* Bs = As + G_TILE;
#pragma unroll
        for (int i = 0; i < 2; i++) {
            const int c = tid + i * 256;             // 0..511
            const int row = c >> 2, kc = (c & 3) * 8;
            cp16(As + row * GPITCH + kc, A  + (size_t)(bm + row) * K + k0 + kc);
        }
#pragma unroll
        for (int i = 0; i < 2; i++) {
            const int c = tid + i * 256;
            const int row = c >> 2, kc = (c & 3) * 8;
            cp16(Bs + row * GPITCH + kc, Bt + (size_t)(bn + row) * K + k0 + kc);
        }
    };

    // prologue: 3 stages in flight
    issue(0);
    asm volatile("cp.async.commit_group;\n");
    if (KT > 1) { issue(1); asm volatile("cp.async.commit_group;\n"); }
    if (KT > 2) { issue(2); asm volatile("cp.async.commit_group;\n"); }

    for (int kt = 0; kt < KT; kt++) {
        // wait for stage kt's group; keep up to 2 newer groups in flight
        if (kt + 2 < KT)      asm volatile("cp.async.wait_group 2;\n");
        else if (kt + 1 < KT) asm volatile("cp.async.wait_group 1;\n");
        else                  asm volatile("cp.async.wait_group 0;\n");
        __syncthreads();   // stage kt visible to all warps; also proves all warps
                           // finished reading stage (kt-1)%4, which issue(kt+3) reuses
        if (kt + 3 < KT) { issue(kt + 3); asm volatile("cp.async.commit_group;\n"); }

        const uint32_t As_u = smem_u32 + ((kt & 3) * G_STAGE) * 2;
        const uint32_t Bs_u = As_u + G_TILE * 2;

#pragma unroll
        for (int ks = 0; ks < 2; ks++) {
            // B fragments: 2 ldmatrix.x4 cover 4 n8-tiles
            uint32_t rb[4][2];
#pragma unroll
            for (int a = 0; a < 2; a++) {
                const int n_ = wn + a * 16 + (mat >> 1) * 8 + mrow;
                const int k_ = ks * 16 + (mat & 1) * 8;
                uint32_t r0, r1, r2, r3;
                ldsm4(r0, r1, r2, r3, Bs_u + (uint32_t)(n_ * GPITCH + k_) * 2);
                rb[2 * a][0] = r0; rb[2 * a][1] = r1;
                rb[2 * a + 1][0] = r2; rb[2 * a + 1][1] = r3;
            }
            // A fragments: 4 ldmatrix.x4 (one per 16-row m tile)
            uint32_t ra[4][4];
#pragma unroll
            for (int mi = 0; mi < 4; mi++) {
                const int m_ = wm + mi * 16 + ((mat & 1) ? 8 : 0) + mrow;
                const int k_ = ks * 16 + ((mat >> 1) ? 8 : 0);
                ldsm4(ra[mi][0], ra[mi][1], ra[mi][2], ra[mi][3],
                      As_u + (uint32_t)(m_ * GPITCH + k_) * 2);
            }
#pragma unroll
            for (int mi = 0; mi < 4; mi++)
#pragma unroll
                for (int ni = 0; ni < 4; ni++)
                    mma_f16(acc[mi][ni], ra[mi][0], ra[mi][1], ra[mi][2], ra[mi][3],
                            rb[ni][0], rb[ni][1]);
        }
        // no trailing barrier: next iteration's start barrier provides the ordering
    }

    // ---- epilogue ----
#pragma unroll
    for (int mi = 0; mi < 4; mi++) {
        const int row0 = bm + wm + mi * 16 + gr;
        const int row1 = row0 + 8;
#pragma unroll
        for (int ni = 0; ni < 4; ni++) {
            const int col = bn + wn + ni * 8 + 2 * tg;
            float v0 = acc[mi][ni][0], v1 = acc[mi][ni][1];
            float v2 = acc[mi][ni][2], v3 = acc[mi][ni][3];
            if (EPI == 1) {
                const float bb0 = bias[col], bb1 = bias[col + 1];
                v0 = gelu_exact(v0 + bb0); v1 = gelu_exact(v1 + bb1);
                v2 = gelu_exact(v2 + bb0); v3 = gelu_exact(v3 + bb1);
            }
            if (EPI == 2) {
                const float bb0 = bias[col], bb1 = bias[col + 1];
                const float2 r0 = *reinterpret_cast<const float2*>(&res[(size_t)row0 * N + col]);
                const float2 r1 = *reinterpret_cast<const float2*>(&res[(size_t)row1 * N + col]);
                v0 += bb0 + r0.x; v1 += bb1 + r0.y;
                v2 += bb0 + r1.x; v3 += bb1 + r1.y;
                *reinterpret_cast<float2*>(&Cf[(size_t)row0 * N + col]) = make_float2(v0, v1);
                *reinterpret_cast<float2*>(&Cf[(size_t)row1 * N + col]) = make_float2(v2, v3);
            } else {
                *reinterpret_cast<__half2*>(&Ch[(size_t)row0 * N + col]) =
                    __floats2half2_rn(v0, v1);
                *reinterpret_cast<__half2*>(&Ch[(size_t)row1 * N + col]) =
                    __floats2half2_rn(v2, v3);
            }
        }
    }
}

// ============ fp16 tensor-core causal flash attention (R7-exact) ============
#define QPITCH 72
#define KPITCH 72
#define ATT_SMEM ((128*QPITCH + 64*KPITCH + 64*KPITCH + 128*QPITCH) * 2)

__global__ void __launch_bounds__(256) attn_kernel(
    const __half* __restrict__ qkv, __half* __restrict__ O)
{
    const int qt = blockIdx.x;
    const int bh = blockIdx.y;
    const int bb = bh >> 4, hh = bh & 15;
    const int tid = threadIdx.x;
    const int lane = tid & 31, wid = tid >> 5;
    const int gr = lane >> 2, tg = lane & 3;
    const int mat = lane >> 3, mrow = lane & 7;
    const size_t rowbase = (size_t)bb * TSEQ;
    const int qoff = hh * DH;
    const int koff = DM + hh * DH;
    const int voff = 2 * DM + hh * DH;
    const int q0 = qt * 128;
    const int wr = wid * 16;

    extern __shared__ __half smh[];
    __half* Qs = smh;                       // [128][QPITCH]
    __half* Ks = Qs + 128 * QPITCH;         // [kcol 64][KPITCH] (natural)
    __half* Vs = Ks + 64 * KPITCH;          // [kk 64][KPITCH]   (natural)
    __half* Ps = Vs + 64 * KPITCH;          // [128][QPITCH]
    const uint32_t Qs_u = (uint32_t)__cvta_generic_to_shared(Qs);
    const uint32_t Ks_u = (uint32_t)__cvta_generic_to_shared(Ks);
    const uint32_t Vs_u = (uint32_t)__cvta_generic_to_shared(Vs);
    const uint32_t Ps_u = (uint32_t)__cvta_generic_to_shared(Ps);

    // load Q tile (scale by 1/8, exact)
    {
        const __half2 sc = __floats2half2_rn(0.125f, 0.125f);
        for (int e = tid; e < 128 * 32; e += 256) {
            const int r = e >> 5, d2 = e & 31;
            __half2 v = *reinterpret_cast<const __half2*>(
                &qkv[(rowbase + q0 + r) * (size_t)(3 * DM) + qoff + 2 * d2]);
            *reinterpret_cast<__half2*>(&Qs[r * QPITCH + 2 * d2]) = __hmul2(v, sc);
        }
    }

    float oacc[8][4];
    float sacc[8][4];
#pragma unroll
    for (int i = 0; i < 8; i++)
#pragma unroll
        for (int r = 0; r < 4; r++) oacc[i][r] = 0.f;
    float m0 = -1e30f, m1 = -1e30f, l0 = 0.f, l1 = 0.f;

    const int kt_max = 2 * qt + 1;
    for (int kt = 0; kt <= kt_max; kt++) {
        const int k0 = kt * 64;
        __syncthreads();
        for (int e = tid; e < 64 * 32; e += 256) {
            const int r = e >> 5, d2 = e & 31;
            const size_t base = (rowbase + k0 + r) * (size_t)(3 * DM);
            *reinterpret_cast<__half2*>(&Ks[r * KPITCH + 2 * d2]) =
                *reinterpret_cast<const __half2*>(&qkv[base + koff + 2 * d2]);
            *reinterpret_cast<__half2*>(&Vs[r * KPITCH + 2 * d2]) =
                *reinterpret_cast<const __half2*>(&qkv[base + voff + 2 * d2]);
        }
        __syncthreads();

        // ---- S = Q K^T ----
#pragma unroll
        for (int i = 0; i < 8; i++)
#pragma unroll
            for (int r = 0; r < 4; r++) sacc[i][r] = 0.f;
#pragma unroll
        for (int ks = 0; ks < 4; ks++) {
            uint32_t a0, a1, a2, a3;
            {
                const int m_ = wr + ((mat & 1) ? 8 : 0) + mrow;
                const int k_ = ks * 16 + ((mat >> 1) ? 8 : 0);
                ldsm4(a0, a1, a2, a3, Qs_u + (uint32_t)(m_ * QPITCH + k_) * 2);
            }
#pragma unroll
            for (int a = 0; a < 4; a++) {
                const int n_ = a * 16 + (mat >> 1) * 8 + mrow;   // kcol
                const int d_ = ks * 16 + (mat & 1) * 8;
                uint32_t b0, b1, b2, b3;
                ldsm4(b0, b1, b2, b3, Ks_u + (uint32_t)(n_ * KPITCH + d_) * 2);
                mma_f16(sacc[2 * a],     a0, a1, a2, a3, b0, b1);
                mma_f16(sacc[2 * a + 1], a0, a1, a2, a3, b2, b3);
            }
        }

        // ---- causal mask ----
        const int row_g0 = q0 + wr + gr, row_g1 = row_g0 + 8;
        if (kt >= 2 * qt) {
#pragma unroll
            for (int ni = 0; ni < 8; ni++) {
                const int c0 = k0 + ni * 8 + 2 * tg, c1 = c0 + 1;
                if (c0 > row_g0) sacc[ni][0] = -1e30f;
                if (c1 > row_g0) sacc[ni][1] = -1e30f;
                if (c0 > row_g1) sacc[ni][2] = -1e30f;
                if (c1 > row_g1) sacc[ni][3] = -1e30f;
            }
        }

        // ---- online softmax ----
        float mx0 = -1e30f, mx1 = -1e30f;
#pragma unroll
        for (int ni = 0; ni < 8; ni++) {
            mx0 = fmaxf(mx0, fmaxf(sacc[ni][0], sacc[ni][1]));
            mx1 = fmaxf(mx1, fmaxf(sacc[ni][2], sacc[ni][3]));
        }
        mx0 = fmaxf(mx0, __shfl_xor_sync(0xffffffffu, mx0, 1));
        mx0 = fmaxf(mx0, __shfl_xor_sync(0xffffffffu, mx0, 2));
        mx1 = fmaxf(mx1, __shfl_xor_sync(0xffffffffu, mx1, 1));
        mx1 = fmaxf(mx1, __shfl_xor_sync(0xffffffffu, mx1, 2));
        const float mn0 = fmaxf(m0, mx0), mn1 = fmaxf(m1, mx1);
        const float al0 = __expf(m0 - mn0), al1 = __expf(m1 - mn1);
        float rs0 = 0.f, rs1 = 0.f;
#pragma unroll
        for (int ni = 0; ni < 8; ni++) {
            float p00 = __expf(sacc[ni][0] - mn0);
            float p01 = __expf(sacc[ni][1] - mn0);
            float p10 = __expf(sacc[ni][2] - mn1);
            float p11 = __expf(sacc[ni][3] - mn1);
            rs0 += p00 + p01; rs1 += p10 + p11;
            const int c = ni * 8 + 2 * tg;
            *reinterpret_cast<__half2*>(&Ps[(wr + gr)     * QPITCH + c]) =
                __floats2half2_rn(p00, p01);
            *reinterpret_cast<__half2*>(&Ps[(wr + gr + 8) * QPITCH + c]) =
                __floats2half2_rn(p10, p11);
        }
        rs0 += __shfl_xor_sync(0xffffffffu, rs0, 1);
        rs0 += __shfl_xor_sync(0xffffffffu, rs0, 2);
        rs1 += __shfl_xor_sync(0xffffffffu, rs1, 1);
        rs1 += __shfl_xor_sync(0xffffffffu, rs1, 2);
        l0 = l0 * al0 + rs0; l1 = l1 * al1 + rs1;
        m0 = mn0; m1 = mn1;
#pragma unroll
        for (int ni = 0; ni < 8; ni++) {
            oacc[ni][0] *= al0; oacc[ni][1] *= al0;
            oacc[ni][2] *= al1; oacc[ni][3] *= al1;
        }
        __syncthreads();

        // ---- O += P V ----
#pragma unroll
        for (int ks = 0; ks < 4; ks++) {
            uint32_t a0, a1, a2, a3;
            {
                const int m_ = wr + ((mat & 1) ? 8 : 0) + mrow;
                const int k_ = ks * 16 + ((mat >> 1) ? 8 : 0);
                ldsm4(a0, a1, a2, a3, Ps_u + (uint32_t)(m_ * QPITCH + k_) * 2);
            }
#pragma unroll
            for (int a = 0; a < 4; a++) {
                const int kk_ = ks * 16 + (mat & 1) * 8 + mrow;
                const int d_  = a * 16 + (mat >> 1) * 8;
                uint32_t b0, b1, b2, b3;
                ldsm4t(b0, b1, b2, b3, Vs_u + (uint32_t)(kk_ * KPITCH + d_) * 2);
                mma_f16(oacc[2 * a],     a0, a1, a2, a3, b0, b1);
                mma_f16(oacc[2 * a + 1], a0, a1, a2, a3, b2, b3);
            }
        }
    }

    // ---- write O (fp16) ----
    const float i0 = 1.0f / l0, i1 = 1.0f / l1;
    const size_t r0 = (rowbase + q0 + wr + gr) * (size_t)DM + hh * DH;
    const size_t r1 = r0 + 8 * DM;
#pragma unroll
    for (int ni = 0; ni < 8; ni++) {
        const int c = ni * 8 + 2 * tg;
        *reinterpret_cast<__half2*>(&O[r0 + c]) =
            __floats2half2_rn(oacc[ni][0] * i0, oacc[ni][1] * i0);
        *reinterpret_cast<__half2*>(&O[r1 + c]) =
            __floats2half2_rn(oacc[ni][2] * i1, oacc[ni][3] * i1);
    }
}

// ---------------- launcher ----------------
extern "C" void kernel_launch(void* const* d_in, const int* in_sizes, int n_in,
                              void* d_out, int out_size)
{
    const float* x     = (const float*)d_in[0];
    const float* ln1_g = (const float*)d_in[1];
    const float* ln1_b = (const float*)d_in[2];
    const float* w_qkv = (const float*)d_in[3];
    const float* w_out = (const float*)d_in[4];
    const float* b_out = (const float*)d_in[5];
    const float* ln2_g = (const float*)d_in[6];
    const float* ln2_b = (const float*)d_in[7];
    const float* w1    = (const float*)d_in[8];
    const float* b1    = (const float*)d_in[9];
    const float* w2    = (const float*)d_in[10];
    const float* b2    = (const float*)d_in[11];
    float* out = (float*)d_out;

    __half *h, *qkv, *o, *ff, *wc;
    float *x2;
    cudaGetSymbolAddress((void**)&h,   g_h);
    cudaGetSymbolAddress((void**)&qkv, g_qkv);
    cudaGetSymbolAddress((void**)&o,   g_o);
    cudaGetSymbolAddress((void**)&x2,  g_x2);
    cudaGetSymbolAddress((void**)&ff,  g_ff);
    cudaGetSymbolAddress((void**)&wc,  g_wc);

    __half* wqkv_t = wc;                       // [3072][1024]
    __half* wout_t = wqkv_t + DM * 3 * DM;     // [1024][1024]
    __half* w1_t   = wout_t + DM * DM;         // [4096][1024]
    __half* w2_t   = w1_t + DM * DFF;          // [1024][4096]

    cudaFuncSetAttribute(attn_kernel,
                         cudaFuncAttributeMaxDynamicSharedMemorySize, ATT_SMEM);
    cudaFuncSetAttribute(gemm_f16<0>,
                         cudaFuncAttributeMaxDynamicSharedMemorySize, GEMM_SMEM);
    cudaFuncSetAttribute(gemm_f16<1>,
                         cudaFuncAttributeMaxDynamicSharedMemorySize, GEMM_SMEM);
    cudaFuncSetAttribute(gemm_f16<2>,
                         cudaFuncAttributeMaxDynamicSharedMemorySize, GEMM_SMEM);

    // 0) weights: transpose + convert to fp16 ([n][k])
    transpose_h_kernel<<<dim3(3*DM/32, DM/32), dim3(32,8)>>>(w_qkv, wqkv_t, DM, 3*DM);
    transpose_h_kernel<<<dim3(DM/32,   DM/32), dim3(32,8)>>>(w_out, wout_t, DM, DM);
    transpose_h_kernel<<<dim3(DFF/32,  DM/32), dim3(32,8)>>>(w1,    w1_t,   DM, DFF);
    transpose_h_kernel<<<dim3(DM/32,  DFF/32), dim3(32,8)>>>(w2,    w2_t,   DFF, DM);

    // 1) h = LN1(x)
    ln_kernel<<<NTOK, 256>>>(x, ln1_g, ln1_b, h);
    // 2) qkv = h @ w_qkv
    gemm_f16<0><<<dim3(3 * DM / 128, NTOK / 128), 256, GEMM_SMEM>>>(
        h, wqkv_t, nullptr, nullptr, nullptr, qkv, NTOK, 3 * DM, DM);
    // 3) o = causal_attention(qkv)
    attn_kernel<<<dim3(TSEQ / 128, 4 * NH), 256, ATT_SMEM>>>(qkv, o);
    // 4) x2 = x + o @ w_out + b_out  (fp32 out)
    gemm_f16<2><<<dim3(DM / 128, NTOK / 128), 256, GEMM_SMEM>>>(
        o, wout_t, b_out, x, x2, nullptr, NTOK, DM, DM);
    // 5) h = LN2(x2)
    ln_kernel<<<NTOK, 256>>>(x2, ln2_g, ln2_b, h);
    // 6) ff = gelu(h @ w1 + b1)
    gemm_f16<1><<<dim3(DFF / 128, NTOK / 128), 256, GEMM_SMEM>>>(
        h, w1_t, b1, nullptr, nullptr, ff, NTOK, DFF, DM);
    // 7) out = x2 + ff @ w2 + b2  (fp32 out)
    gemm_f16<2><<<dim3(DM / 128, NTOK / 128), 256, GEMM_SMEM>>>(
        ff, w2_t, b2, x2, out, nullptr, NTOK, DM, DFF);
}

// round 11
// speedup vs baseline: 1.0585x; 1.0585x over previous
#include <cuda_runtime.h>
#include <cuda_fp16.h>
#include <math.h>
#include <stdint.h>

#define NTOK   8192      // B*T
#define DM     1024
#define DFF    4096
#define TSEQ   2048
#define NH     16
#define DH     64

// ---------------- scratch (static device globals; no allocation) ----------------
__device__ __half g_h  [NTOK * DM];       // LN output (fp16)
__device__ __half g_qkv[NTOK * 3 * DM];   // qkv projections (fp16)
__device__ __half g_o  [NTOK * DM];       // attention output (fp16)
__device__ float  g_x2 [NTOK * DM];       // residual after attention (fp32)
__device__ __half g_ff [NTOK * DFF];      // gelu output (fp16)
__device__ __half g_wc [DM*3*DM + DM*DM + DM*DFF + DFF*DM]; // fp16 weights, [n][k]

// ---------------- fused weight transpose + fp16 convert (all 4 weights) ----------
// out[n][k] = h(in[k][n]). Linear block id decodes which weight / which 32x32 tile.
__global__ void __launch_bounds__(256) transpose_all_kernel(
    const float* __restrict__ w0, const float* __restrict__ w1,
    const float* __restrict__ w2, const float* __restrict__ w3,
    __half* __restrict__ d0, __half* __restrict__ d1,
    __half* __restrict__ d2, __half* __restrict__ d3)
{
    __shared__ float tile[32][33];
    const int bid = blockIdx.x;
    const float* in; __half* out; int K, N, nx, local;
    if (bid < 3072)      { in = w0; out = d0; K = 1024; N = 3072; nx = 96;  local = bid; }
    else if (bid < 4096) { in = w1; out = d1; K = 1024; N = 1024; nx = 32;  local = bid - 3072; }
    else if (bid < 8192) { in = w2; out = d2; K = 1024; N = 4096; nx = 128; local = bid - 4096; }
    else                 { in = w3; out = d3; K = 4096; N = 1024; nx = 32;  local = bid - 8192; }
    const int n0 = (local % nx) * 32, k0 = (local / nx) * 32;
    const int tx = threadIdx.x, ty = threadIdx.y;   // block (32, 8)
#pragma unroll
    for (int i = 0; i < 4; i++)
        tile[ty + i * 8][tx] = in[(size_t)(k0 + ty + i * 8) * N + n0 + tx];
    __syncthreads();
#pragma unroll
    for (int i = 0; i < 4; i++)
        out[(size_t)(n0 + ty + i * 8) * K + k0 + tx] =
            __float2half_rn(tile[tx][ty + i * 8]);
}

// ---------------- LayerNorm: fp32 in -> fp16 out ----------------
__global__ void __launch_bounds__(256) ln_kernel(
    const float* __restrict__ x, const float* __restrict__ g,
    const float* __restrict__ b, __half* __restrict__ out)
{
    const int row = blockIdx.x;
    const float* xr = x + (size_t)row * DM;
    float v[4];
    float s = 0.f, s2 = 0.f;
#pragma unroll
    for (int i = 0; i < 4; i++) {
        v[i] = xr[threadIdx.x + i * 256];
        s += v[i]; s2 += v[i] * v[i];
    }
#pragma unroll
    for (int off = 16; off; off >>= 1) {
        s  += __shfl_xor_sync(0xffffffffu, s,  off);
        s2 += __shfl_xor_sync(0xffffffffu, s2, off);
    }
    __shared__ float ss[8], ss2[8];
    const int w = threadIdx.x >> 5, ln = threadIdx.x & 31;
    if (ln == 0) { ss[w] = s; ss2[w] = s2; }
    __syncthreads();
    s = 0.f; s2 = 0.f;
#pragma unroll
    for (int i = 0; i < 8; i++) { s += ss[i]; s2 += ss2[i]; }
    const float mean = s * (1.0f / DM);
    const float var  = s2 * (1.0f / DM) - mean * mean;
    const float rstd = rsqrtf(var + 1e-5f);
    __half* orow = out + (size_t)row * DM;
#pragma unroll
    for (int i = 0; i < 4; i++) {
        const int c = threadIdx.x + i * 256;
        orow[c] = __float2half_rn((v[i] - mean) * rstd * g[c] + b[c]);
    }
}

// ================ fp16 tensor-core GEMM (R7-exact: 3-stage, 128x128) ================
__device__ __forceinline__ float gelu_exact(float x) {
    return 0.5f * x * (1.0f + erff(x * 0.70710678118654752f));
}
__device__ __forceinline__ void ldsm4(uint32_t& r0, uint32_t& r1,
                                      uint32_t& r2, uint32_t& r3, uint32_t addr) {
    asm volatile("ldmatrix.sync.aligned.m8n8.x4.shared.b16 {%0,%1,%2,%3}, [%4];\n"
                 : "=r"(r0), "=r"(r1), "=r"(r2), "=r"(r3) : "r"(addr));
}
__device__ __forceinline__ void ldsm4t(uint32_t& r0, uint32_t& r1,
                                       uint32_t& r2, uint32_t& r3, uint32_t addr) {
    asm volatile("ldmatrix.sync.aligned.m8n8.x4.trans.shared.b16 {%0,%1,%2,%3}, [%4];\n"
                 : "=r"(r0), "=r"(r1), "=r"(r2), "=r"(r3) : "r"(addr));
}
__device__ __forceinline__ void mma_f16(float* c,
    uint32_t a0, uint32_t a1, uint32_t a2, uint32_t a3, uint32_t b0, uint32_t b1) {
    asm volatile(
        "mma.sync.aligned.m16n8k16.row.col.f32.f16.f16.f32 "
        "{%0,%1,%2,%3}, {%4,%5,%6,%7}, {%8,%9}, {%0,%1,%2,%3};\n"
        : "+f"(c[0]), "+f"(c[1]), "+f"(c[2]), "+f"(c[3])
        : "r"(a0), "r"(a1), "r"(a2), "r"(a3), "r"(b0), "r"(b1));
}
__device__ __forceinline__ void cp16(__half* dst, const __half* src) {
    uint32_t d = (uint32_t)__cvta_generic_to_shared(dst);
    asm volatile("cp.async.cg.shared.global [%0], [%1], 16;\n" :: "r"(d), "l"(src));
}

#define GPITCH 40                       // halves per smem row (64B data + 16B pad)
#define G_TILE (128 * GPITCH)           // halves per operand tile
#define G_STAGE (2 * G_TILE)            // halves per stage (A + B)
#define GEMM_SMEM (3 * G_STAGE * 2)     // bytes (= 61440)

template<int EPI>
__global__ void __launch_bounds__(256) gemm_f16(
    const __half* __restrict__ A, const __half* __restrict__ Bt,
    const float* __restrict__ bias, const float* __restrict__ res,
    float* __restrict__ Cf, __half* __restrict__ Ch, int M, int N, int K)
{
    extern __shared__ __half smh[];
    const int tid  = threadIdx.x;
    const int lane = tid & 31, wid = tid >> 5;
    const int bm = blockIdx.y * 128, bn = blockIdx.x * 128;
    const int wm = (wid >> 2) * 64;
    const int wn = (wid & 3) * 32;
    const int gr = lane >> 2, tg = lane & 3;

    const uint32_t smem_u32 = (uint32_t)__cvta_generic_to_shared(smh);
    const int mat  = lane >> 3;
    const int mrow = lane & 7;

    float acc[4][4][4];
#pragma unroll
    for (int i = 0; i < 4; i++)
#pragma unroll
        for (int j = 0; j < 4; j++)
#pragma unroll
            for (int r = 0; r < 4; r++) acc[i][j][r] = 0.f;

    const int KT = K >> 5;

    auto issue = [&](int kt) {
        const int stg = kt % 3;
        const int k0 = kt << 5;
        __half* As = smh + stg * G_STAGE;
        __half* Bs = As + G_TILE;
#pragma unroll
        for (int i = 0; i < 2; i++) {
            const int c = tid + i * 256;
            const int row = c >> 2, kc = (c & 3) * 8;
            cp16(As + row * GPITCH + kc, A  + (size_t)(bm + row) * K + k0 + kc);
        }
#pragma unroll
        for (int i = 0; i < 2; i++) {
            const int c = tid + i * 256;
            const int row = c >> 2, kc = (c & 3) * 8;
            cp16(Bs + row * GPITCH + kc, Bt + (size_t)(bn + row) * K + k0 + kc);
        }
    };

    issue(0);
    asm volatile("cp.async.commit_group;\n");
    if (KT > 1) { issue(1); asm volatile("cp.async.commit_group;\n"); }

    for (int kt = 0; kt < KT; kt++) {
        const int cur = kt % 3;
        if (kt + 1 < KT) asm volatile("cp.async.wait_group 1;\n");
        else             asm volatile("cp.async.wait_group 0;\n");
        __syncthreads();
        if (kt + 2 < KT) { issue(kt + 2); asm volatile("cp.async.commit_group;\n"); }

        const uint32_t As_u = smem_u32 + (cur * G_STAGE) * 2;
        const uint32_t Bs_u = As_u + G_TILE * 2;

#pragma unroll
        for (int ks = 0; ks < 2; ks++) {
            uint32_t rb[4][2];
#pragma unroll
            for (int a = 0; a < 2; a++) {
                const int n_ = wn + a * 16 + (mat >> 1) * 8 + mrow;
                const int k_ = ks * 16 + (mat & 1) * 8;
                uint32_t r0, r1, r2, r3;
                ldsm4(r0, r1, r2, r3, Bs_u + (uint32_t)(n_ * GPITCH + k_) * 2);
                rb[2 * a][0] = r0; rb[2 * a][1] = r1;
                rb[2 * a + 1][0] = r2; rb[2 * a + 1][1] = r3;
            }
            uint32_t ra[4][4];
#pragma unroll
            for (int mi = 0; mi < 4; mi++) {
                const int m_ = wm + mi * 16 + ((mat & 1) ? 8 : 0) + mrow;
                const int k_ = ks * 16 + ((mat >> 1) ? 8 : 0);
                ldsm4(ra[mi][0], ra[mi][1], ra[mi][2], ra[mi][3],
                      As_u + (uint32_t)(m_ * GPITCH + k_) * 2);
            }
#pragma unroll
            for (int mi = 0; mi < 4; mi++)
#pragma unroll
                for (int ni = 0; ni < 4; ni++)
                    mma_f16(acc[mi][ni], ra[mi][0], ra[mi][1], ra[mi][2], ra[mi][3],
                            rb[ni][0], rb[ni][1]);
        }
        __syncthreads();
    }

    // ---- epilogue ----
#pragma unroll
    for (int mi = 0; mi < 4; mi++) {
        const int row0 = bm + wm + mi * 16 + gr;
        const int row1 = row0 + 8;
#pragma unroll
        for (int ni = 0; ni < 4; ni++) {
            const int col = bn + wn + ni * 8 + 2 * tg;
            float v0 = acc[mi][ni][0], v1 = acc[mi][ni][1];
            float v2 = acc[mi][ni][2], v3 = acc[mi][ni][3];
            if (EPI == 1) {
                const float bb0 = bias[col], bb1 = bias[col + 1];
                v0 = gelu_exact(v0 + bb0); v1 = gelu_exact(v1 + bb1);
                v2 = gelu_exact(v2 + bb0); v3 = gelu_exact(v3 + bb1);
            }
            if (EPI == 2) {
                const float bb0 = bias[col], bb1 = bias[col + 1];
                const float2 r0 = *reinterpret_cast<const float2*>(&res[(size_t)row0 * N + col]);
                const float2 r1 = *reinterpret_cast<const float2*>(&res[(size_t)row1 * N + col]);
                v0 += bb0 + r0.x; v1 += bb1 + r0.y;
                v2 += bb0 + r1.x; v3 += bb1 + r1.y;
                *reinterpret_cast<float2*>(&Cf[(size_t)row0 * N + col]) = make_float2(v0, v1);
                *reinterpret_cast<float2*>(&Cf[(size_t)row1 * N + col]) = make_float2(v2, v3);
            } else {
                *reinterpret_cast<__half2*>(&Ch[(size_t)row0 * N + col]) =
                    __floats2half2_rn(v0, v1);
                *reinterpret_cast<__half2*>(&Ch[(size_t)row1 * N + col]) =
                    __floats2half2_rn(v2, v3);
            }
        }
    }
}

// ============ fp16 tensor-core causal flash attention ============
// K/V tiles double-buffered via cp.async: prefetch tile kt+1 during compute of kt.
#define QPITCH 72
#define KPITCH 72
#define KV_STAGE (64 * KPITCH)          // halves per K (or V) stage
#define ATT_SMEM ((128*QPITCH + 2*KV_STAGE + 2*KV_STAGE + 128*QPITCH) * 2)

__global__ void __launch_bounds__(256) attn_kernel(
    const __half* __restrict__ qkv, __half* __restrict__ O)
{
    const int qt = blockIdx.x;
    const int bh = blockIdx.y;
    const int bb = bh >> 4, hh = bh & 15;
    const int tid = threadIdx.x;
    const int lane = tid & 31, wid = tid >> 5;
    const int gr = lane >> 2, tg = lane & 3;
    const int mat = lane >> 3, mrow = lane & 7;
    const size_t rowbase = (size_t)bb * TSEQ;
    const int qoff = hh * DH;
    const int koff = DM + hh * DH;
    const int voff = 2 * DM + hh * DH;
    const int q0 = qt * 128;
    const int wr = wid * 16;

    extern __shared__ __half smh[];
    __half* Qs = smh;                           // [128][QPITCH]
    __half* Ks = Qs + 128 * QPITCH;             // 2 x [64][KPITCH]
    __half* Vs = Ks + 2 * KV_STAGE;             // 2 x [64][KPITCH]
    __half* Ps = Vs + 2 * KV_STAGE;             // [128][QPITCH]
    const uint32_t Qs_u = (uint32_t)__cvta_generic_to_shared(Qs);
    const uint32_t Ks_u = (uint32_t)__cvta_generic_to_shared(Ks);
    const uint32_t Vs_u = (uint32_t)__cvta_generic_to_shared(Vs);
    const uint32_t Ps_u = (uint32_t)__cvta_generic_to_shared(Ps);

    // load Q tile (scale by 1/8, exact)
    {
        const __half2 sc = __floats2half2_rn(0.125f, 0.125f);
        for (int e = tid; e < 128 * 32; e += 256) {
            const int r = e >> 5, d2 = e & 31;
            __half2 v = *reinterpret_cast<const __half2*>(
                &qkv[(rowbase + q0 + r) * (size_t)(3 * DM) + qoff + 2 * d2]);
            *reinterpret_cast<__half2*>(&Qs[r * QPITCH + 2 * d2]) = __hmul2(v, sc);
        }
    }

    // async K/V stage loader: 1024 x 16B granules, 4 per thread
    auto issue_kv = [&](int kt) {
        const int s = kt & 1;
        const int k0 = kt * 64;
        __half* Kd = Ks + s * KV_STAGE;
        __half* Vd = Vs + s * KV_STAGE;
#pragma unroll
        for (int i = 0; i < 4; i++) {
            const int c = tid + i * 256;          // 0..1023
            const int sel = c >> 9;               // 0 = K, 1 = V
            const int r = (c >> 3) & 63;
            const int kc = (c & 7) * 8;           // halves (16B granule)
            const size_t base = (rowbase + k0 + r) * (size_t)(3 * DM);
            if (sel == 0) cp16(Kd + r * KPITCH + kc, qkv + base + koff + kc);
            else          cp16(Vd + r * KPITCH + kc, qkv + base + voff + kc);
        }
    };

    float oacc[8][4];
    float sacc[8][4];
#pragma unroll
    for (int i = 0; i < 8; i++)
#pragma unroll
        for (int r = 0; r < 4; r++) oacc[i][r] = 0.f;
    float m0 = -1e30f, m1 = -1e30f, l0 = 0.f, l1 = 0.f;

    const int kt_max = 2 * qt + 1;
    issue_kv(0);
    asm volatile("cp.async.commit_group;\n");

    for (int kt = 0; kt <= kt_max; kt++) {
        __syncthreads();   // all warps done reading stage (kt+1)&1 from iteration kt-1
        if (kt < kt_max) {
            issue_kv(kt + 1);
            asm volatile("cp.async.commit_group;\n");
            asm volatile("cp.async.wait_group 1;\n");
        } else {
            asm volatile("cp.async.wait_group 0;\n");
        }
        __syncthreads();   // stage kt visible to all warps

        const uint32_t Ksu = Ks_u + (uint32_t)((kt & 1) * KV_STAGE) * 2;
        const uint32_t Vsu = Vs_u + (uint32_t)((kt & 1) * KV_STAGE) * 2;
        const int k0 = kt * 64;

        // ---- S = Q K^T ----
#pragma unroll
        for (int i = 0; i < 8; i++)
#pragma unroll
            for (int r = 0; r < 4; r++) sacc[i][r] = 0.f;
#pragma unroll
        for (int ks = 0; ks < 4; ks++) {
            uint32_t a0, a1, a2, a3;
            {
                const int m_ = wr + ((mat & 1) ? 8 : 0) + mrow;
                const int k_ = ks * 16 + ((mat >> 1) ? 8 : 0);
                ldsm4(a0, a1, a2, a3, Qs_u + (uint32_t)(m_ * QPITCH + k_) * 2);
            }
#pragma unroll
            for (int a = 0; a < 4; a++) {
                const int n_ = a * 16 + (mat >> 1) * 8 + mrow;
                const int d_ = ks * 16 + (mat & 1) * 8;
                uint32_t b0, b1, b2, b3;
                ldsm4(b0, b1, b2, b3, Ksu + (uint32_t)(n_ * KPITCH + d_) * 2);
                mma_f16(sacc[2 * a],     a0, a1, a2, a3, b0, b1);
                mma_f16(sacc[2 * a + 1], a0, a1, a2, a3, b2, b3);
            }
        }

        // ---- causal mask ----
        const int row_g0 = q0 + wr + gr, row_g1 = row_g0 + 8;
        if (kt >= 2 * qt) {
#pragma unroll
            for (int ni = 0; ni < 8; ni++) {
                const int c0 = k0 + ni * 8 + 2 * tg, c1 = c0 + 1;
                if (c0 > row_g0) sacc[ni][0] = -1e30f;
                if (c1 > row_g0) sacc[ni][1] = -1e30f;
                if (c0 > row_g1) sacc[ni][2] = -1e30f;
                if (c1 > row_g1) sacc[ni][3] = -1e30f;
            }
        }

        // ---- online softmax ----
        float mx0 = -1e30f, mx1 = -1e30f;
#pragma unroll
        for (int ni = 0; ni < 8; ni++) {
            mx0 = fmaxf(mx0, fmaxf(sacc[ni][0], sacc[ni][1]));
            mx1 = fmaxf(mx1, fmaxf(sacc[ni][2], sacc[ni][3]));
        }
        mx0 = fmaxf(mx0, __shfl_xor_sync(0xffffffffu, mx0, 1));
        mx0 = fmaxf(mx0, __shfl_xor_sync(0xffffffffu, mx0, 2));
        mx1 = fmaxf(mx1, __shfl_xor_sync(0xffffffffu, mx1, 1));
        mx1 = fmaxf(mx1, __shfl_xor_sync(0xffffffffu, mx1, 2));
        const float mn0 = fmaxf(m0, mx0), mn1 = fmaxf(m1, mx1);
        const float al0 = __expf(m0 - mn0), al1 = __expf(m1 - mn1);
        float rs0 = 0.f, rs1 = 0.f;
#pragma unroll
        for (int ni = 0; ni < 8; ni++) {
            float p00 = __expf(sacc[ni][0] - mn0);
            float p01 = __expf(sacc[ni][1] - mn0);
            float p10 = __expf(sacc[ni][2] - mn1);
            float p11 = __expf(sacc[ni][3] - mn1);
            rs0 += p00 + p01; rs1 += p10 + p11;
            const int c = ni * 8 + 2 * tg;
            *reinterpret_cast<__half2*>(&Ps[(wr + gr)     * QPITCH + c]) =
                __floats2half2_rn(p00, p01);
            *reinterpret_cast<__half2*>(&Ps[(wr + gr + 8) * QPITCH + c]) =
                __floats2half2_rn(p10, p11);
        }
        rs0 += __shfl_xor_sync(0xffffffffu, rs0, 1);
        rs0 += __shfl_xor_sync(0xffffffffu, rs0, 2);
        rs1 += __shfl_xor_sync(0xffffffffu, rs1, 1);
        rs1 += __shfl_xor_sync(0xffffffffu, rs1, 2);
        l0 = l0 * al0 + rs0; l1 = l1 * al1 + rs1;
        m0 = mn0; m1 = mn1;
#pragma unroll
        for (int ni = 0; ni < 8; ni++) {
            oacc[ni][0] *= al0; oacc[ni][1] *= al0;
            oacc[ni][2] *= al1; oacc[ni][3] *= al1;
        }
        __syncthreads();

        // ---- O += P V ----
#pragma unroll
        for (int ks = 0; ks < 4; ks++) {
            uint32_t a0, a1, a2, a3;
            {
                const int m_ = wr + ((mat & 1) ? 8 : 0) + mrow;
                const int k_ = ks * 16 + ((mat >> 1) ? 8 : 0);
                ldsm4(a0, a1, a2, a3, Ps_u + (uint32_t)(m_ * QPITCH + k_) * 2);
            }
#pragma unroll
            for (int a = 0; a < 4; a++) {
                const int kk_ = ks * 16 + (mat & 1) * 8 + mrow;
                const int d_  = a * 16 + (mat >> 1) * 8;
                uint32_t b0, b1, b2, b3;
                ldsm4t(b0, b1, b2, b3, Vsu + (uint32_t)(kk_ * KPITCH + d_) * 2);
                mma_f16(oacc[2 * a],     a0, a1, a2, a3, b0, b1);
                mma_f16(oacc[2 * a + 1], a0, a1, a2, a3, b2, b3);
            }
        }
    }

    // ---- write O (fp16) ----
    const float i0 = 1.0f / l0, i1 = 1.0f / l1;
    const size_t r0 = (rowbase + q0 + wr + gr) * (size_t)DM + hh * DH;
    const size_t r1 = r0 + 8 * DM;
#pragma unroll
    for (int ni = 0; ni < 8; ni++) {
        const int c = ni * 8 + 2 * tg;
        *reinterpret_cast<__half2*>(&O[r0 + c]) =
            __floats2half2_rn(oacc[ni][0] * i0, oacc[ni][1] * i0);
        *reinterpret_cast<__half2*>(&O[r1 + c]) =
            __floats2half2_rn(oacc[ni][2] * i1, oacc[ni][3] * i1);
    }
}

// ---------------- launcher ----------------
extern "C" void kernel_launch(void* const* d_in, const int* in_sizes, int n_in,
                              void* d_out, int out_size)
{
    const float* x     = (const float*)d_in[0];
    const float* ln1_g = (const float*)d_in[1];
    const float* ln1_b = (const float*)d_in[2];
    const float* w_qkv = (const float*)d_in[3];
    const float* w_out = (const float*)d_in[4];
    const float* b_out = (const float*)d_in[5];
    const float* ln2_g = (const float*)d_in[6];
    const float* ln2_b = (const float*)d_in[7];
    const float* w1    = (const float*)d_in[8];
    const float* b1    = (const float*)d_in[9];
    const float* w2    = (const float*)d_in[10];
    const float* b2    = (const float*)d_in[11];
    float* out = (float*)d_out;

    __half *h, *qkv, *o, *ff, *wc;
    float *x2;
    cudaGetSymbolAddress((void**)&h,   g_h);
    cudaGetSymbolAddress((void**)&qkv, g_qkv);
    cudaGetSymbolAddress((void**)&o,   g_o);
    cudaGetSymbolAddress((void**)&x2,  g_x2);
    cudaGetSymbolAddress((void**)&ff,  g_ff);
    cudaGetSymbolAddress((void**)&wc,  g_wc);

    __half* wqkv_t = wc;                       // [3072][1024]
    __half* wout_t = wqkv_t + DM * 3 * DM;     // [1024][1024]
    __half* w1_t   = wout_t + DM * DM;         // [4096][1024]
    __half* w2_t   = w1_t + DM * DFF;          // [1024][4096]

    cudaFuncSetAttribute(attn_kernel,
                         cudaFuncAttributeMaxDynamicSharedMemorySize, ATT_SMEM);
    cudaFuncSetAttribute(gemm_f16<0>,
                         cudaFuncAttributeMaxDynamicSharedMemorySize, GEMM_SMEM);
    cudaFuncSetAttribute(gemm_f16<1>,
                         cudaFuncAttributeMaxDynamicSharedMemorySize, GEMM_SMEM);
    cudaFuncSetAttribute(gemm_f16<2>,
                         cudaFuncAttributeMaxDynamicSharedMemorySize, GEMM_SMEM);

    // 0) all 4 weight transposes in ONE launch
    transpose_all_kernel<<<12288, dim3(32, 8)>>>(
        w_qkv, w_out, w1, w2, wqkv_t, wout_t, w1_t, w2_t);

    // 1) h = LN1(x)
    ln_kernel<<<NTOK, 256>>>(x, ln1_g, ln1_b, h);
    // 2) qkv = h @ w_qkv
    gemm_f16<0><<<dim3(3 * DM / 128, NTOK / 128), 256, GEMM_SMEM>>>(
        h, wqkv_t, nullptr, nullptr, nullptr, qkv, NTOK, 3 * DM, DM);
    // 3) o = causal_attention(qkv)
    attn_kernel<<<dim3(TSEQ / 128, 4 * NH), 256, ATT_SMEM>>>(qkv, o);
    // 4) x2 = x + o @ w_out + b_out  (fp32 out)
    gemm_f16<2><<<dim3(DM / 128, NTOK / 128), 256, GEMM_SMEM>>>(
        o, wout_t, b_out, x, x2, nullptr, NTOK, DM, DM);
    // 5) h = LN2(x2)
    ln_kernel<<<NTOK, 256>>>(x2, ln2_g, ln2_b, h);
    // 6) ff = gelu(h @ w1 + b1)
    gemm_f16<1><<<dim3(DFF / 128, NTOK / 128), 256, GEMM_SMEM>>>(
        h, w1_t, b1, nullptr, nullptr, ff, NTOK, DFF, DM);
    // 7) out = x2 + ff @ w2 + b2  (fp32 out)
    gemm_f16<2><<<dim3(DM / 128, NTOK / 128), 256, GEMM_SMEM>>>(
        ff, w2_t, b2, x2, out, nullptr, NTOK, DM, DFF);
}

// round 13
// speedup vs baseline: 1.0626x; 1.0038x over previous
#include <cuda_runtime.h>
#include <cuda_fp16.h>
#include <math.h>
#include <stdint.h>

#define NTOK   8192      // B*T
#define DM     1024
#define DFF    4096
#define TSEQ   2048
#define NH     16
#define DH     64

// ---------------- scratch (static device globals; no allocation) ----------------
__device__ __half g_h  [NTOK * DM];       // LN output (fp16)
__device__ __half g_qkv[NTOK * 3 * DM];   // qkv projections (fp16)
__device__ __half g_o  [NTOK * DM];       // attention output (fp16)
__device__ float  g_x2 [NTOK * DM];       // residual after attention (fp32)
__device__ __half g_ff [NTOK * DFF];      // gelu output (fp16)
__device__ __half g_wc [DM*3*DM + DM*DM + DM*DFF + DFF*DM]; // fp16 weights, [n][k]

// ---------------- fused weight transpose + fp16 convert (all 4 weights) ----------
__global__ void __launch_bounds__(256) transpose_all_kernel(
    const float* __restrict__ w0, const float* __restrict__ w1,
    const float* __restrict__ w2, const float* __restrict__ w3,
    __half* __restrict__ d0, __half* __restrict__ d1,
    __half* __restrict__ d2, __half* __restrict__ d3)
{
    __shared__ float tile[32][33];
    const int bid = blockIdx.x;
    const float* in; __half* out; int K, N, nx, local;
    if (bid < 3072)      { in = w0; out = d0; K = 1024; N = 3072; nx = 96;  local = bid; }
    else if (bid < 4096) { in = w1; out = d1; K = 1024; N = 1024; nx = 32;  local = bid - 3072; }
    else if (bid < 8192) { in = w2; out = d2; K = 1024; N = 4096; nx = 128; local = bid - 4096; }
    else                 { in = w3; out = d3; K = 4096; N = 1024; nx = 32;  local = bid - 8192; }
    const int n0 = (local % nx) * 32, k0 = (local / nx) * 32;
    const int tx = threadIdx.x, ty = threadIdx.y;   // block (32, 8)
#pragma unroll
    for (int i = 0; i < 4; i++)
        tile[ty + i * 8][tx] = in[(size_t)(k0 + ty + i * 8) * N + n0 + tx];
    __syncthreads();
#pragma unroll
    for (int i = 0; i < 4; i++)
        out[(size_t)(n0 + ty + i * 8) * K + k0 + tx] =
            __float2half_rn(tile[tx][ty + i * 8]);
}

// ---------------- LayerNorm: fp32 in -> fp16 out (vectorized) ----------------
__global__ void __launch_bounds__(256) ln_kernel(
    const float* __restrict__ x, const float* __restrict__ g,
    const float* __restrict__ b, __half* __restrict__ out)
{
    const int row = blockIdx.x;
    const int t4 = threadIdx.x * 4;
    const float4 v = *reinterpret_cast<const float4*>(x + (size_t)row * DM + t4);
    float s  = v.x + v.y + v.z + v.w;
    float s2 = v.x * v.x + v.y * v.y + v.z * v.z + v.w * v.w;
#pragma unroll
    for (int off = 16; off; off >>= 1) {
        s  += __shfl_xor_sync(0xffffffffu, s,  off);
        s2 += __shfl_xor_sync(0xffffffffu, s2, off);
    }
    __shared__ float ss[8], ss2[8];
    const int w = threadIdx.x >> 5, ln = threadIdx.x & 31;
    if (ln == 0) { ss[w] = s; ss2[w] = s2; }
    __syncthreads();
    s = 0.f; s2 = 0.f;
#pragma unroll
    for (int i = 0; i < 8; i++) { s += ss[i]; s2 += ss2[i]; }
    const float mean = s * (1.0f / DM);
    const float var  = s2 * (1.0f / DM) - mean * mean;
    const float rstd = rsqrtf(var + 1e-5f);
    const float4 gv = *reinterpret_cast<const float4*>(g + t4);
    const float4 bv = *reinterpret_cast<const float4*>(b + t4);
    __half2 h01 = __floats2half2_rn((v.x - mean) * rstd * gv.x + bv.x,
                                    (v.y - mean) * rstd * gv.y + bv.y);
    __half2 h23 = __floats2half2_rn((v.z - mean) * rstd * gv.z + bv.z,
                                    (v.w - mean) * rstd * gv.w + bv.w);
    __half2* orow = reinterpret_cast<__half2*>(out + (size_t)row * DM + t4);
    orow[0] = h01;
    orow[1] = h23;
}

// ================ fp16 tensor-core GEMM (R7-exact: 3-stage, 128x128) ================
__device__ __forceinline__ float gelu_exact(float x) {
    return 0.5f * x * (1.0f + erff(x * 0.70710678118654752f));
}
__device__ __forceinline__ void ldsm4(uint32_t& r0, uint32_t& r1,
                                      uint32_t& r2, uint32_t& r3, uint32_t addr) {
    asm volatile("ldmatrix.sync.aligned.m8n8.x4.shared.b16 {%0,%1,%2,%3}, [%4];\n"
                 : "=r"(r0), "=r"(r1), "=r"(r2), "=r"(r3) : "r"(addr));
}
__device__ __forceinline__ void ldsm4t(uint32_t& r0, uint32_t& r1,
                                       uint32_t& r2, uint32_t& r3, uint32_t addr) {
    asm volatile("ldmatrix.sync.aligned.m8n8.x4.trans.shared.b16 {%0,%1,%2,%3}, [%4];\n"
                 : "=r"(r0), "=r"(r1), "=r"(r2), "=r"(r3) : "r"(addr));
}
__device__ __forceinline__ void mma_f16(float* c,
    uint32_t a0, uint32_t a1, uint32_t a2, uint32_t a3, uint32_t b0, uint32_t b1) {
    asm volatile(
        "mma.sync.aligned.m16n8k16.row.col.f32.f16.f16.f32 "
        "{%0,%1,%2,%3}, {%4,%5,%6,%7}, {%8,%9}, {%0,%1,%2,%3};\n"
        : "+f"(c[0]), "+f"(c[1]), "+f"(c[2]), "+f"(c[3])
        : "r"(a0), "r"(a1), "r"(a2), "r"(a3), "r"(b0), "r"(b1));
}
__device__ __forceinline__ void cp16(__half* dst, const __half* src) {
    uint32_t d = (uint32_t)__cvta_generic_to_shared(dst);
    asm volatile("cp.async.cg.shared.global [%0], [%1], 16;\n" :: "r"(d), "l"(src));
}

#define GPITCH 40                       // halves per smem row (64B data + 16B pad)
#define G_TILE (128 * GPITCH)           // halves per operand tile
#define G_STAGE (2 * G_TILE)            // halves per stage (A + B)
#define GEMM_SMEM (3 * G_STAGE * 2)     // bytes (= 61440)

template<int EPI>
__global__ void __launch_bounds__(256) gemm_f16(
    const __half* __restrict__ A, const __half* __restrict__ Bt,
    const float* __restrict__ bias, const float* __restrict__ res,
    float* __restrict__ Cf, __half* __restrict__ Ch, int M, int N, int K)
{
    extern __shared__ __half smh[];
    const int tid  = threadIdx.x;
    const int lane = tid & 31, wid = tid >> 5;
    const int bm = blockIdx.y * 128, bn = blockIdx.x * 128;
    const int wm = (wid >> 2) * 64;
    const int wn = (wid & 3) * 32;
    const int gr = lane >> 2, tg = lane & 3;

    const uint32_t smem_u32 = (uint32_t)__cvta_generic_to_shared(smh);
    const int mat  = lane >> 3;
    const int mrow = lane & 7;

    float acc[4][4][4];
#pragma unroll
    for (int i = 0; i < 4; i++)
#pragma unroll
        for (int j = 0; j < 4; j++)
#pragma unroll
            for (int r = 0; r < 4; r++) acc[i][j][r] = 0.f;

    const int KT = K >> 5;

    auto issue = [&](int kt) {
        const int stg = kt % 3;
        const int k0 = kt << 5;
        __half* As = smh + stg * G_STAGE;
        __half* Bs = As + G_TILE;
#pragma unroll
        for (int i = 0; i < 2; i++) {
            const int c = tid + i * 256;
            const int row = c >> 2, kc = (c & 3) * 8;
            cp16(As + row * GPITCH + kc, A  + (size_t)(bm + row) * K + k0 + kc);
        }
#pragma unroll
        for (int i = 0; i < 2; i++) {
            const int c = tid + i * 256;
            const int row = c >> 2, kc = (c & 3) * 8;
            cp16(Bs + row * GPITCH + kc, Bt + (size_t)(bn + row) * K + k0 + kc);
        }
    };

    issue(0);
    asm volatile("cp.async.commit_group;\n");
    if (KT > 1) { issue(1); asm volatile("cp.async.commit_group;\n"); }

    for (int kt = 0; kt < KT; kt++) {
        const int cur = kt % 3;
        if (kt + 1 < KT) asm volatile("cp.async.wait_group 1;\n");
        else             asm volatile("cp.async.wait_group 0;\n");
        __syncthreads();
        if (kt + 2 < KT) { issue(kt + 2); asm volatile("cp.async.commit_group;\n"); }

        const uint32_t As_u = smem_u32 + (cur * G_STAGE) * 2;
        const uint32_t Bs_u = As_u + G_TILE * 2;

#pragma unroll
        for (int ks = 0; ks < 2; ks++) {
            uint32_t rb[4][2];
#pragma unroll
            for (int a = 0; a < 2; a++) {
                const int n_ = wn + a * 16 + (mat >> 1) * 8 + mrow;
                const int k_ = ks * 16 + (mat & 1) * 8;
                uint32_t r0, r1, r2, r3;
                ldsm4(r0, r1, r2, r3, Bs_u + (uint32_t)(n_ * GPITCH + k_) * 2);
                rb[2 * a][0] = r0; rb[2 * a][1] = r1;
                rb[2 * a + 1][0] = r2; rb[2 * a + 1][1] = r3;
            }
            uint32_t ra[4][4];
#pragma unroll
            for (int mi = 0; mi < 4; mi++) {
                const int m_ = wm + mi * 16 + ((mat & 1) ? 8 : 0) + mrow;
                const int k_ = ks * 16 + ((mat >> 1) ? 8 : 0);
                ldsm4(ra[mi][0], ra[mi][1], ra[mi][2], ra[mi][3],
                      As_u + (uint32_t)(m_ * GPITCH + k_) * 2);
            }
#pragma unroll
            for (int mi = 0; mi < 4; mi++)
#pragma unroll
                for (int ni = 0; ni < 4; ni++)
                    mma_f16(acc[mi][ni], ra[mi][0], ra[mi][1], ra[mi][2], ra[mi][3],
                            rb[ni][0], rb[ni][1]);
        }
        __syncthreads();
    }

    // ---- epilogue ----
#pragma unroll
    for (int mi = 0; mi < 4; mi++) {
        const int row0 = bm + wm + mi * 16 + gr;
        const int row1 = row0 + 8;
#pragma unroll
        for (int ni = 0; ni < 4; ni++) {
            const int col = bn + wn + ni * 8 + 2 * tg;
            float v0 = acc[mi][ni][0], v1 = acc[mi][ni][1];
            float v2 = acc[mi][ni][2], v3 = acc[mi][ni][3];
            if (EPI == 1) {
                const float bb0 = bias[col], bb1 = bias[col + 1];
                v0 = gelu_exact(v0 + bb0); v1 = gelu_exact(v1 + bb1);
                v2 = gelu_exact(v2 + bb0); v3 = gelu_exact(v3 + bb1);
            }
            if (EPI == 2) {
                const float bb0 = bias[col], bb1 = bias[col + 1];
                const float2 r0 = *reinterpret_cast<const float2*>(&res[(size_t)row0 * N + col]);
                const float2 r1 = *reinterpret_cast<const float2*>(&res[(size_t)row1 * N + col]);
                v0 += bb0 + r0.x; v1 += bb1 + r0.y;
                v2 += bb0 + r1.x; v3 += bb1 + r1.y;
                *reinterpret_cast<float2*>(&Cf[(size_t)row0 * N + col]) = make_float2(v0, v1);
                *reinterpret_cast<float2*>(&Cf[(size_t)row1 * N + col]) = make_float2(v2, v3);
            } else {
                *reinterpret_cast<__half2*>(&Ch[(size_t)row0 * N + col]) =
                    __floats2half2_rn(v0, v1);
                *reinterpret_cast<__half2*>(&Ch[(size_t)row1 * N + col]) =
                    __floats2half2_rn(v2, v3);
            }
        }
    }
}

// ============ fp16 tensor-core causal flash attention ============
// K/V double-buffered cp.async; HEAVY-FIRST scheduling (qt reversed vs blockIdx.x).
#define QPITCH 72
#define KPITCH 72
#define KV_STAGE (64 * KPITCH)          // halves per K (or V) stage
#define ATT_SMEM ((128*QPITCH + 2*KV_STAGE + 2*KV_STAGE + 128*QPITCH) * 2)

__global__ void __launch_bounds__(256) attn_kernel(
    const __half* __restrict__ qkv, __half* __restrict__ O)
{
    const int qt = gridDim.x - 1 - blockIdx.x;   // heavy tiles scheduled first
    const int bh = blockIdx.y;
    const int bb = bh >> 4, hh = bh & 15;
    const int tid = threadIdx.x;
    const int lane = tid & 31, wid = tid >> 5;
    const int gr = lane >> 2, tg = lane & 3;
    const int mat = lane >> 3, mrow = lane & 7;
    const size_t rowbase = (size_t)bb * TSEQ;
    const int qoff = hh * DH;
    const int koff = DM + hh * DH;
    const int voff = 2 * DM + hh * DH;
    const int q0 = qt * 128;
    const int wr = wid * 16;

    extern __shared__ __half smh[];
    __half* Qs = smh;                           // [128][QPITCH]
    __half* Ks = Qs + 128 * QPITCH;             // 2 x [64][KPITCH]
    __half* Vs = Ks + 2 * KV_STAGE;             // 2 x [64][KPITCH]
    __half* Ps = Vs + 2 * KV_STAGE;             // [128][QPITCH]
    const uint32_t Qs_u = (uint32_t)__cvta_generic_to_shared(Qs);
    const uint32_t Ks_u = (uint32_t)__cvta_generic_to_shared(Ks);
    const uint32_t Vs_u = (uint32_t)__cvta_generic_to_shared(Vs);
    const uint32_t Ps_u = (uint32_t)__cvta_generic_to_shared(Ps);

    // load Q tile (scale by 1/8, exact)
    {
        const __half2 sc = __floats2half2_rn(0.125f, 0.125f);
        for (int e = tid; e < 128 * 32; e += 256) {
            const int r = e >> 5, d2 = e & 31;
            __half2 v = *reinterpret_cast<const __half2*>(
                &qkv[(rowbase + q0 + r) * (size_t)(3 * DM) + qoff + 2 * d2]);
            *reinterpret_cast<__half2*>(&Qs[r * QPITCH + 2 * d2]) = __hmul2(v, sc);
        }
    }

    // async K/V stage loader
    auto issue_kv = [&](int kt) {
        const int s = kt & 1;
        const int k0 = kt * 64;
        __half* Kd = Ks + s * KV_STAGE;
        __half* Vd = Vs + s * KV_STAGE;
#pragma unroll
        for (int i = 0; i < 4; i++) {
            const int c = tid + i * 256;          // 0..1023
            const int sel = c >> 9;               // 0 = K, 1 = V
            const int r = (c >> 3) & 63;
            const int kc = (c & 7) * 8;
            const size_t base = (rowbase + k0 + r) * (size_t)(3 * DM);
            if (sel == 0) cp16(Kd + r * KPITCH + kc, qkv + base + koff + kc);
            else          cp16(Vd + r * KPITCH + kc, qkv + base + voff + kc);
        }
    };

    float oacc[8][4];
    float sacc[8][4];
#pragma unroll
    for (int i = 0; i < 8; i++)
#pragma unroll
        for (int r = 0; r < 4; r++) oacc[i][r] = 0.f;
    float m0 = -1e30f, m1 = -1e30f, l0 = 0.f, l1 = 0.f;

    const int kt_max = 2 * qt + 1;
    issue_kv(0);
    asm volatile("cp.async.commit_group;\n");

    for (int kt = 0; kt <= kt_max; kt++) {
        __syncthreads();
        if (kt < kt_max) {
            issue_kv(kt + 1);
            asm volatile("cp.async.commit_group;\n");
            asm volatile("cp.async.wait_group 1;\n");
        } else {
            asm volatile("cp.async.wait_group 0;\n");
        }
        __syncthreads();

        const uint32_t Ksu = Ks_u + (uint32_t)((kt & 1) * KV_STAGE) * 2;
        const uint32_t Vsu = Vs_u + (uint32_t)((kt & 1) * KV_STAGE) * 2;
        const int k0 = kt * 64;

        // ---- S = Q K^T ----
#pragma unroll
        for (int i = 0; i < 8; i++)
#pragma unroll
            for (int r = 0; r < 4; r++) sacc[i][r] = 0.f;
#pragma unroll
        for (int ks = 0; ks < 4; ks++) {
            uint32_t a0, a1, a2, a3;
            {
                const int m_ = wr + ((mat & 1) ? 8 : 0) + mrow;
                const int k_ = ks * 16 + ((mat >> 1) ? 8 : 0);
                ldsm4(a0, a1, a2, a3, Qs_u + (uint32_t)(m_ * QPITCH + k_) * 2);
            }
#pragma unroll
            for (int a = 0; a < 4; a++) {
                const int n_ = a * 16 + (mat >> 1) * 8 + mrow;
                const int d_ = ks * 16 + (mat & 1) * 8;
                uint32_t b0, b1, b2, b3;
                ldsm4(b0, b1, b2, b3, Ksu + (uint32_t)(n_ * KPITCH + d_) * 2);
                mma_f16(sacc[2 * a],     a0, a1, a2, a3, b0, b1);
                mma_f16(sacc[2 * a + 1], a0, a1, a2, a3, b2, b3);
            }
        }

        // ---- causal mask ----
        const int row_g0 = q0 + wr + gr, row_g1 = row_g0 + 8;
        if (kt >= 2 * qt) {
#pragma unroll
            for (int ni = 0; ni < 8; ni++) {
                const int c0 = k0 + ni * 8 + 2 * tg, c1 = c0 + 1;
                if (c0 > row_g0) sacc[ni][0] = -1e30f;
                if (c1 > row_g0) sacc[ni][1] = -1e30f;
                if (c0 > row_g1) sacc[ni][2] = -1e30f;
                if (c1 > row_g1) sacc[ni][3] = -1e30f;
            }
        }

        // ---- online softmax ----
        float mx0 = -1e30f, mx1 = -1e30f;
#pragma unroll
        for (int ni = 0; ni < 8; ni++) {
            mx0 = fmaxf(mx0, fmaxf(sacc[ni][0], sacc[ni][1]));
            mx1 = fmaxf(mx1, fmaxf(sacc[ni][2], sacc[ni][3]));
        }
        mx0 = fmaxf(mx0, __shfl_xor_sync(0xffffffffu, mx0, 1));
        mx0 = fmaxf(mx0, __shfl_xor_sync(0xffffffffu, mx0, 2));
        mx1 = fmaxf(mx1, __shfl_xor_sync(0xffffffffu, mx1, 1));
        mx1 = fmaxf(mx1, __shfl_xor_sync(0xffffffffu, mx1, 2));
        const float mn0 = fmaxf(m0, mx0), mn1 = fmaxf(m1, mx1);
        const float al0 = __expf(m0 - mn0), al1 = __expf(m1 - mn1);
        float rs0 = 0.f, rs1 = 0.f;
#pragma unroll
        for (int ni = 0; ni < 8; ni++) {
            float p00 = __expf(sacc[ni][0] - mn0);
            float p01 = __expf(sacc[ni][1] - mn0);
            float p10 = __expf(sacc[ni][2] - mn1);
            float p11 = __expf(sacc[ni][3] - mn1);
            rs0 += p00 + p01; rs1 += p10 + p11;
            const int c = ni * 8 + 2 * tg;
            *reinterpret_cast<__half2*>(&Ps[(wr + gr)     * QPITCH + c]) =
                __floats2half2_rn(p00, p01);
            *reinterpret_cast<__half2*>(&Ps[(wr + gr + 8) * QPITCH + c]) =
                __floats2half2_rn(p10, p11);
        }
        rs0 += __shfl_xor_sync(0xffffffffu, rs0, 1);
        rs0 += __shfl_xor_sync(0xffffffffu, rs0, 2);
        rs1 += __shfl_xor_sync(0xffffffffu, rs1, 1);
        rs1 += __shfl_xor_sync(0xffffffffu, rs1, 2);
        l0 = l0 * al0 + rs0; l1 = l1 * al1 + rs1;
        m0 = mn0; m1 = mn1;
#pragma unroll
        for (int ni = 0; ni < 8; ni++) {
            oacc[ni][0] *= al0; oacc[ni][1] *= al0;
            oacc[ni][2] *= al1; oacc[ni][3] *= al1;
        }
        __syncthreads();

        // ---- O += P V ----
#pragma unroll
        for (int ks = 0; ks < 4; ks++) {
            uint32_t a0, a1, a2, a3;
            {
                const int m_ = wr + ((mat & 1) ? 8 : 0) + mrow;
                const int k_ = ks * 16 + ((mat >> 1) ? 8 : 0);
                ldsm4(a0, a1, a2, a3, Ps_u + (uint32_t)(m_ * QPITCH + k_) * 2);
            }
#pragma unroll
            for (int a = 0; a < 4; a++) {
                const int kk_ = ks * 16 + (mat & 1) * 8 + mrow;
                const int d_  = a * 16 + (mat >> 1) * 8;
                uint32_t b0, b1, b2, b3;
                ldsm4t(b0, b1, b2, b3, Vsu + (uint32_t)(kk_ * KPITCH + d_) * 2);
                mma_f16(oacc[2 * a],     a0, a1, a2, a3, b0, b1);
                mma_f16(oacc[2 * a + 1], a0, a1, a2, a3, b2, b3);
            }
        }
    }

    // ---- write O (fp16) ----
    const float i0 = 1.0f / l0, i1 = 1.0f / l1;
    const size_t r0 = (rowbase + q0 + wr + gr) * (size_t)DM + hh * DH;
    const size_t r1 = r0 + 8 * DM;
#pragma unroll
    for (int ni = 0; ni < 8; ni++) {
        const int c = ni * 8 + 2 * tg;
        *reinterpret_cast<__half2*>(&O[r0 + c]) =
            __floats2half2_rn(oacc[ni][0] * i0, oacc[ni][1] * i0);
        *reinterpret_cast<__half2*>(&O[r1 + c]) =
            __floats2half2_rn(oacc[ni][2] * i1, oacc[ni][3] * i1);
    }
}

// ---------------- launcher ----------------
extern "C" void kernel_launch(void* const* d_in, const int* in_sizes, int n_in,
                              void* d_out, int out_size)
{
    const float* x     = (const float*)d_in[0];
    const float* ln1_g = (const float*)d_in[1];
    const float* ln1_b = (const float*)d_in[2];
    const float* w_qkv = (const float*)d_in[3];
    const float* w_out = (const float*)d_in[4];
    const float* b_out = (const float*)d_in[5];
    const float* ln2_g = (const float*)d_in[6];
    const float* ln2_b = (const float*)d_in[7];
    const float* w1    = (const float*)d_in[8];
    const float* b1    = (const float*)d_in[9];
    const float* w2    = (const float*)d_in[10];
    const float* b2    = (const float*)d_in[11];
    float* out = (float*)d_out;

    __half *h, *qkv, *o, *ff, *wc;
    float *x2;
    cudaGetSymbolAddress((void**)&h,   g_h);
    cudaGetSymbolAddress((void**)&qkv, g_qkv);
    cudaGetSymbolAddress((void**)&o,   g_o);
    cudaGetSymbolAddress((void**)&x2,  g_x2);
    cudaGetSymbolAddress((void**)&ff,  g_ff);
    cudaGetSymbolAddress((void**)&wc,  g_wc);

    __half* wqkv_t = wc;                       // [3072][1024]
    __half* wout_t = wqkv_t + DM * 3 * DM;     // [1024][1024]
    __half* w1_t   = wout_t + DM * DM;         // [4096][1024]
    __half* w2_t   = w1_t + DM * DFF;          // [1024][4096]

    cudaFuncSetAttribute(attn_kernel,
                         cudaFuncAttributeMaxDynamicSharedMemorySize, ATT_SMEM);
    cudaFuncSetAttribute(gemm_f16<0>,
                         cudaFuncAttributeMaxDynamicSharedMemorySize, GEMM_SMEM);
    cudaFuncSetAttribute(gemm_f16<1>,
                         cudaFuncAttributeMaxDynamicSharedMemorySize, GEMM_SMEM);
    cudaFuncSetAttribute(gemm_f16<2>,
                         cudaFuncAttributeMaxDynamicSharedMemorySize, GEMM_SMEM);

    // 0) all 4 weight transposes in ONE launch
    transpose_all_kernel<<<12288, dim3(32, 8)>>>(
        w_qkv, w_out, w1, w2, wqkv_t, wout_t, w1_t, w2_t);

    // 1) h = LN1(x)
    ln_kernel<<<NTOK, 256>>>(x, ln1_g, ln1_b, h);
    // 2) qkv = h @ w_qkv
    gemm_f16<0><<<dim3(3 * DM / 128, NTOK / 128), 256, GEMM_SMEM>>>(
        h, wqkv_t, nullptr, nullptr, nullptr, qkv, NTOK, 3 * DM, DM);
    // 3) o = causal_attention(qkv)   (heavy-first scheduling inside)
    attn_kernel<<<dim3(TSEQ / 128, 4 * NH), 256, ATT_SMEM>>>(qkv, o);
    // 4) x2 = x + o @ w_out + b_out  (fp32 out)
    gemm_f16<2><<<dim3(DM / 128, NTOK / 128), 256, GEMM_SMEM>>>(
        o, wout_t, b_out, x, x2, nullptr, NTOK, DM, DM);
    // 5) h = LN2(x2)
    ln_kernel<<<NTOK, 256>>>(x2, ln2_g, ln2_b, h);
    // 6) ff = gelu(h @ w1 + b1)
    gemm_f16<1><<<dim3(DFF / 128, NTOK / 128), 256, GEMM_SMEM>>>(
        h, w1_t, b1, nullptr, nullptr, ff, NTOK, DFF, DM);
    // 7) out = x2 + ff @ w2 + b2  (fp32 out)
    gemm_f16<2><<<dim3(DM / 128, NTOK / 128), 256, GEMM_SMEM>>>(
        ff, w2_t, b2, x2, out, nullptr, NTOK, DM, DFF);
}

// round 14
// speedup vs baseline: 1.0874x; 1.0233x over previous
#include <cuda_runtime.h>
#include <cuda_fp16.h>
#include <math.h>
#include <stdint.h>

#define NTOK   8192      // B*T
#define DM     1024
#define DFF    4096
#define TSEQ   2048
#define NH     16
#define DH     64

// ---------------- scratch (static device globals; no allocation) ----------------
__device__ __half g_h  [NTOK * DM];       // LN output (fp16)
__device__ __half g_qkv[NTOK * 3 * DM];   // qkv projections (fp16)
__device__ __half g_o  [NTOK * DM];       // attention output (fp16)
__device__ float  g_x2 [NTOK * DM];       // residual after attention (fp32)
__device__ __half g_ff [NTOK * DFF];      // gelu output (fp16)
__device__ __half g_wc [DM*3*DM + DM*DM + DM*DFF + DFF*DM]; // fp16 weights, [n][k]

// ---------------- fused weight transpose + fp16 convert (all 4 weights) ----------
__global__ void __launch_bounds__(256) transpose_all_kernel(
    const float* __restrict__ w0, const float* __restrict__ w1,
    const float* __restrict__ w2, const float* __restrict__ w3,
    __half* __restrict__ d0, __half* __restrict__ d1,
    __half* __restrict__ d2, __half* __restrict__ d3)
{
    __shared__ float tile[32][33];
    const int bid = blockIdx.x;
    const float* in; __half* out; int K, N, nx, local;
    if (bid < 3072)      { in = w0; out = d0; K = 1024; N = 3072; nx = 96;  local = bid; }
    else if (bid < 4096) { in = w1; out = d1; K = 1024; N = 1024; nx = 32;  local = bid - 3072; }
    else if (bid < 8192) { in = w2; out = d2; K = 1024; N = 4096; nx = 128; local = bid - 4096; }
    else                 { in = w3; out = d3; K = 4096; N = 1024; nx = 32;  local = bid - 8192; }
    const int n0 = (local % nx) * 32, k0 = (local / nx) * 32;
    const int tx = threadIdx.x, ty = threadIdx.y;   // block (32, 8)
#pragma unroll
    for (int i = 0; i < 4; i++)
        tile[ty + i * 8][tx] = in[(size_t)(k0 + ty + i * 8) * N + n0 + tx];
    __syncthreads();
#pragma unroll
    for (int i = 0; i < 4; i++)
        out[(size_t)(n0 + ty + i * 8) * K + k0 + tx] =
            __float2half_rn(tile[tx][ty + i * 8]);
}

// ---------------- LayerNorm: fp32 in -> fp16 out (vectorized) ----------------
__global__ void __launch_bounds__(256) ln_kernel(
    const float* __restrict__ x, const float* __restrict__ g,
    const float* __restrict__ b, __half* __restrict__ out)
{
    const int row = blockIdx.x;
    const int t4 = threadIdx.x * 4;
    const float4 v = *reinterpret_cast<const float4*>(x + (size_t)row * DM + t4);
    float s  = v.x + v.y + v.z + v.w;
    float s2 = v.x * v.x + v.y * v.y + v.z * v.z + v.w * v.w;
#pragma unroll
    for (int off = 16; off; off >>= 1) {
        s  += __shfl_xor_sync(0xffffffffu, s,  off);
        s2 += __shfl_xor_sync(0xffffffffu, s2, off);
    }
    __shared__ float ss[8], ss2[8];
    const int w = threadIdx.x >> 5, ln = threadIdx.x & 31;
    if (ln == 0) { ss[w] = s; ss2[w] = s2; }
    __syncthreads();
    s = 0.f; s2 = 0.f;
#pragma unroll
    for (int i = 0; i < 8; i++) { s += ss[i]; s2 += ss2[i]; }
    const float mean = s * (1.0f / DM);
    const float var  = s2 * (1.0f / DM) - mean * mean;
    const float rstd = rsqrtf(var + 1e-5f);
    const float4 gv = *reinterpret_cast<const float4*>(g + t4);
    const float4 bv = *reinterpret_cast<const float4*>(b + t4);
    __half2 h01 = __floats2half2_rn((v.x - mean) * rstd * gv.x + bv.x,
                                    (v.y - mean) * rstd * gv.y + bv.y);
    __half2 h23 = __floats2half2_rn((v.z - mean) * rstd * gv.z + bv.z,
                                    (v.w - mean) * rstd * gv.w + bv.w);
    __half2* orow = reinterpret_cast<__half2*>(out + (size_t)row * DM + t4);
    orow[0] = h01;
    orow[1] = h23;
}

// ================ fp16 tensor-core GEMM (R7-exact: 3-stage, 128x128) ================
__device__ __forceinline__ float gelu_exact(float x) {
    return 0.5f * x * (1.0f + erff(x * 0.70710678118654752f));
}
__device__ __forceinline__ void ldsm4(uint32_t& r0, uint32_t& r1,
                                      uint32_t& r2, uint32_t& r3, uint32_t addr) {
    asm volatile("ldmatrix.sync.aligned.m8n8.x4.shared.b16 {%0,%1,%2,%3}, [%4];\n"
                 : "=r"(r0), "=r"(r1), "=r"(r2), "=r"(r3) : "r"(addr));
}
__device__ __forceinline__ void ldsm4t(uint32_t& r0, uint32_t& r1,
                                       uint32_t& r2, uint32_t& r3, uint32_t addr) {
    asm volatile("ldmatrix.sync.aligned.m8n8.x4.trans.shared.b16 {%0,%1,%2,%3}, [%4];\n"
                 : "=r"(r0), "=r"(r1), "=r"(r2), "=r"(r3) : "r"(addr));
}
__device__ __forceinline__ void mma_f16(float* c,
    uint32_t a0, uint32_t a1, uint32_t a2, uint32_t a3, uint32_t b0, uint32_t b1) {
    asm volatile(
        "mma.sync.aligned.m16n8k16.row.col.f32.f16.f16.f32 "
        "{%0,%1,%2,%3}, {%4,%5,%6,%7}, {%8,%9}, {%0,%1,%2,%3};\n"
        : "+f"(c[0]), "+f"(c[1]), "+f"(c[2]), "+f"(c[3])
        : "r"(a0), "r"(a1), "r"(a2), "r"(a3), "r"(b0), "r"(b1));
}
__device__ __forceinline__ void cp16(__half* dst, const __half* src) {
    uint32_t d = (uint32_t)__cvta_generic_to_shared(dst);
    asm volatile("cp.async.cg.shared.global [%0], [%1], 16;\n" :: "r"(d), "l"(src));
}
__device__ __forceinline__ uint32_t h2u(__half2 h) {
    uint32_t u;
    asm("mov.b32 %0, %1;" : "=r"(u) : "r"(*reinterpret_cast<uint32_t*>(&h)));
    return u;
}

#define GPITCH 40                       // halves per smem row (64B data + 16B pad)
#define G_TILE (128 * GPITCH)           // halves per operand tile
#define G_STAGE (2 * G_TILE)            // halves per stage (A + B)
#define GEMM_SMEM (3 * G_STAGE * 2)     // bytes (= 61440)

template<int EPI>
__global__ void __launch_bounds__(256) gemm_f16(
    const __half* __restrict__ A, const __half* __restrict__ Bt,
    const float* __restrict__ bias, const float* __restrict__ res,
    float* __restrict__ Cf, __half* __restrict__ Ch, int M, int N, int K)
{
    extern __shared__ __half smh[];
    const int tid  = threadIdx.x;
    const int lane = tid & 31, wid = tid >> 5;
    const int bm = blockIdx.y * 128, bn = blockIdx.x * 128;
    const int wm = (wid >> 2) * 64;
    const int wn = (wid & 3) * 32;
    const int gr = lane >> 2, tg = lane & 3;

    const uint32_t smem_u32 = (uint32_t)__cvta_generic_to_shared(smh);
    const int mat  = lane >> 3;
    const int mrow = lane & 7;

    float acc[4][4][4];
#pragma unroll
    for (int i = 0; i < 4; i++)
#pragma unroll
        for (int j = 0; j < 4; j++)
#pragma unroll
            for (int r = 0; r < 4; r++) acc[i][j][r] = 0.f;

    const int KT = K >> 5;

    auto issue = [&](int kt) {
        const int stg = kt % 3;
        const int k0 = kt << 5;
        __half* As = smh + stg * G_STAGE;
        __half* Bs = As + G_TILE;
#pragma unroll
        for (int i = 0; i < 2; i++) {
            const int c = tid + i * 256;
            const int row = c >> 2, kc = (c & 3) * 8;
            cp16(As + row * GPITCH + kc, A  + (size_t)(bm + row) * K + k0 + kc);
        }
#pragma unroll
        for (int i = 0; i < 2; i++) {
            const int c = tid + i * 256;
            const int row = c >> 2, kc = (c & 3) * 8;
            cp16(Bs + row * GPITCH + kc, Bt + (size_t)(bn + row) * K + k0 + kc);
        }
    };

    issue(0);
    asm volatile("cp.async.commit_group;\n");
    if (KT > 1) { issue(1); asm volatile("cp.async.commit_group;\n"); }

    for (int kt = 0; kt < KT; kt++) {
        const int cur = kt % 3;
        if (kt + 1 < KT) asm volatile("cp.async.wait_group 1;\n");
        else             asm volatile("cp.async.wait_group 0;\n");
        __syncthreads();
        if (kt + 2 < KT) { issue(kt + 2); asm volatile("cp.async.commit_group;\n"); }

        const uint32_t As_u = smem_u32 + (cur * G_STAGE) * 2;
        const uint32_t Bs_u = As_u + G_TILE * 2;

#pragma unroll
        for (int ks = 0; ks < 2; ks++) {
            uint32_t rb[4][2];
#pragma unroll
            for (int a = 0; a < 2; a++) {
                const int n_ = wn + a * 16 + (mat >> 1) * 8 + mrow;
                const int k_ = ks * 16 + (mat & 1) * 8;
                uint32_t r0, r1, r2, r3;
                ldsm4(r0, r1, r2, r3, Bs_u + (uint32_t)(n_ * GPITCH + k_) * 2);
                rb[2 * a][0] = r0; rb[2 * a][1] = r1;
                rb[2 * a + 1][0] = r2; rb[2 * a + 1][1] = r3;
            }
            uint32_t ra[4][4];
#pragma unroll
            for (int mi = 0; mi < 4; mi++) {
                const int m_ = wm + mi * 16 + ((mat & 1) ? 8 : 0) + mrow;
                const int k_ = ks * 16 + ((mat >> 1) ? 8 : 0);
                ldsm4(ra[mi][0], ra[mi][1], ra[mi][2], ra[mi][3],
                      As_u + (uint32_t)(m_ * GPITCH + k_) * 2);
            }
#pragma unroll
            for (int mi = 0; mi < 4; mi++)
#pragma unroll
                for (int ni = 0; ni < 4; ni++)
                    mma_f16(acc[mi][ni], ra[mi][0], ra[mi][1], ra[mi][2], ra[mi][3],
                            rb[ni][0], rb[ni][1]);
        }
        __syncthreads();
    }

    // ---- epilogue ----
#pragma unroll
    for (int mi = 0; mi < 4; mi++) {
        const int row0 = bm + wm + mi * 16 + gr;
        const int row1 = row0 + 8;
#pragma unroll
        for (int ni = 0; ni < 4; ni++) {
            const int col = bn + wn + ni * 8 + 2 * tg;
            float v0 = acc[mi][ni][0], v1 = acc[mi][ni][1];
            float v2 = acc[mi][ni][2], v3 = acc[mi][ni][3];
            if (EPI == 1) {
                const float bb0 = bias[col], bb1 = bias[col + 1];
                v0 = gelu_exact(v0 + bb0); v1 = gelu_exact(v1 + bb1);
                v2 = gelu_exact(v2 + bb0); v3 = gelu_exact(v3 + bb1);
            }
            if (EPI == 2) {
                const float bb0 = bias[col], bb1 = bias[col + 1];
                const float2 r0 = *reinterpret_cast<const float2*>(&res[(size_t)row0 * N + col]);
                const float2 r1 = *reinterpret_cast<const float2*>(&res[(size_t)row1 * N + col]);
                v0 += bb0 + r0.x; v1 += bb1 + r0.y;
                v2 += bb0 + r1.x; v3 += bb1 + r1.y;
                *reinterpret_cast<float2*>(&Cf[(size_t)row0 * N + col]) = make_float2(v0, v1);
                *reinterpret_cast<float2*>(&Cf[(size_t)row1 * N + col]) = make_float2(v2, v3);
            } else {
                *reinterpret_cast<__half2*>(&Ch[(size_t)row0 * N + col]) =
                    __floats2half2_rn(v0, v1);
                *reinterpret_cast<__half2*>(&Ch[(size_t)row1 * N + col]) =
                    __floats2half2_rn(v2, v3);
            }
        }
    }
}

// ============ fp16 tensor-core causal flash attention ============
// K/V double-buffered cp.async; heavy-first scheduling; REGISTER-RESIDENT P
// (S accumulator fragments remapped directly to PV A-operand fragments).
#define QPITCH 72
#define KPITCH 72
#define KV_STAGE (64 * KPITCH)          // halves per K (or V) stage
#define ATT_SMEM ((128*QPITCH + 2*KV_STAGE + 2*KV_STAGE) * 2)

__global__ void __launch_bounds__(256) attn_kernel(
    const __half* __restrict__ qkv, __half* __restrict__ O)
{
    const int qt = gridDim.x - 1 - blockIdx.x;   // heavy tiles scheduled first
    const int bh = blockIdx.y;
    const int bb = bh >> 4, hh = bh & 15;
    const int tid = threadIdx.x;
    const int lane = tid & 31, wid = tid >> 5;
    const int gr = lane >> 2, tg = lane & 3;
    const int mat = lane >> 3, mrow = lane & 7;
    const size_t rowbase = (size_t)bb * TSEQ;
    const int qoff = hh * DH;
    const int koff = DM + hh * DH;
    const int voff = 2 * DM + hh * DH;
    const int q0 = qt * 128;
    const int wr = wid * 16;

    extern __shared__ __half smh[];
    __half* Qs = smh;                           // [128][QPITCH]
    __half* Ks = Qs + 128 * QPITCH;             // 2 x [64][KPITCH]
    __half* Vs = Ks + 2 * KV_STAGE;             // 2 x [64][KPITCH]
    const uint32_t Qs_u = (uint32_t)__cvta_generic_to_shared(Qs);
    const uint32_t Ks_u = (uint32_t)__cvta_generic_to_shared(Ks);
    const uint32_t Vs_u = (uint32_t)__cvta_generic_to_shared(Vs);

    // load Q tile (scale by 1/8, exact)
    {
        const __half2 sc = __floats2half2_rn(0.125f, 0.125f);
        for (int e = tid; e < 128 * 32; e += 256) {
            const int r = e >> 5, d2 = e & 31;
            __half2 v = *reinterpret_cast<const __half2*>(
                &qkv[(rowbase + q0 + r) * (size_t)(3 * DM) + qoff + 2 * d2]);
            *reinterpret_cast<__half2*>(&Qs[r * QPITCH + 2 * d2]) = __hmul2(v, sc);
        }
    }

    // async K/V stage loader
    auto issue_kv = [&](int kt) {
        const int s = kt & 1;
        const int k0 = kt * 64;
        __half* Kd = Ks + s * KV_STAGE;
        __half* Vd = Vs + s * KV_STAGE;
#pragma unroll
        for (int i = 0; i < 4; i++) {
            const int c = tid + i * 256;          // 0..1023
            const int sel = c >> 9;               // 0 = K, 1 = V
            const int r = (c >> 3) & 63;
            const int kc = (c & 7) * 8;
            const size_t base = (rowbase + k0 + r) * (size_t)(3 * DM);
            if (sel == 0) cp16(Kd + r * KPITCH + kc, qkv + base + koff + kc);
            else          cp16(Vd + r * KPITCH + kc, qkv + base + voff + kc);
        }
    };

    float oacc[8][4];
    float sacc[8][4];
    uint32_t pfrag[8][2];               // P as half2 fragments, register-resident
#pragma unroll
    for (int i = 0; i < 8; i++)
#pragma unroll
        for (int r = 0; r < 4; r++) oacc[i][r] = 0.f;
    float m0 = -1e30f, m1 = -1e30f, l0 = 0.f, l1 = 0.f;

    const int kt_max = 2 * qt + 1;
    issue_kv(0);
    asm volatile("cp.async.commit_group;\n");

    for (int kt = 0; kt <= kt_max; kt++) {
        __syncthreads();
        if (kt < kt_max) {
            issue_kv(kt + 1);
            asm volatile("cp.async.commit_group;\n");
            asm volatile("cp.async.wait_group 1;\n");
        } else {
            asm volatile("cp.async.wait_group 0;\n");
        }
        __syncthreads();

        const uint32_t Ksu = Ks_u + (uint32_t)((kt & 1) * KV_STAGE) * 2;
        const uint32_t Vsu = Vs_u + (uint32_t)((kt & 1) * KV_STAGE) * 2;
        const int k0 = kt * 64;

        // ---- S = Q K^T ----
#pragma unroll
        for (int i = 0; i < 8; i++)
#pragma unroll
            for (int r = 0; r < 4; r++) sacc[i][r] = 0.f;
#pragma unroll
        for (int ks = 0; ks < 4; ks++) {
            uint32_t a0, a1, a2, a3;
            {
                const int m_ = wr + ((mat & 1) ? 8 : 0) + mrow;
                const int k_ = ks * 16 + ((mat >> 1) ? 8 : 0);
                ldsm4(a0, a1, a2, a3, Qs_u + (uint32_t)(m_ * QPITCH + k_) * 2);
            }
#pragma unroll
            for (int a = 0; a < 4; a++) {
                const int n_ = a * 16 + (mat >> 1) * 8 + mrow;
                const int d_ = ks * 16 + (mat & 1) * 8;
                uint32_t b0, b1, b2, b3;
                ldsm4(b0, b1, b2, b3, Ksu + (uint32_t)(n_ * KPITCH + d_) * 2);
                mma_f16(sacc[2 * a],     a0, a1, a2, a3, b0, b1);
                mma_f16(sacc[2 * a + 1], a0, a1, a2, a3, b2, b3);
            }
        }

        // ---- causal mask ----
        const int row_g0 = q0 + wr + gr, row_g1 = row_g0 + 8;
        if (kt >= 2 * qt) {
#pragma unroll
            for (int ni = 0; ni < 8; ni++) {
                const int c0 = k0 + ni * 8 + 2 * tg, c1 = c0 + 1;
                if (c0 > row_g0) sacc[ni][0] = -1e30f;
                if (c1 > row_g0) sacc[ni][1] = -1e30f;
                if (c0 > row_g1) sacc[ni][2] = -1e30f;
                if (c1 > row_g1) sacc[ni][3] = -1e30f;
            }
        }

        // ---- online softmax; P -> half2 register fragments ----
        float mx0 = -1e30f, mx1 = -1e30f;
#pragma unroll
        for (int ni = 0; ni < 8; ni++) {
            mx0 = fmaxf(mx0, fmaxf(sacc[ni][0], sacc[ni][1]));
            mx1 = fmaxf(mx1, fmaxf(sacc[ni][2], sacc[ni][3]));
        }
        mx0 = fmaxf(mx0, __shfl_xor_sync(0xffffffffu, mx0, 1));
        mx0 = fmaxf(mx0, __shfl_xor_sync(0xffffffffu, mx0, 2));
        mx1 = fmaxf(mx1, __shfl_xor_sync(0xffffffffu, mx1, 1));
        mx1 = fmaxf(mx1, __shfl_xor_sync(0xffffffffu, mx1, 2));
        const float mn0 = fmaxf(m0, mx0), mn1 = fmaxf(m1, mx1);
        const float al0 = __expf(m0 - mn0), al1 = __expf(m1 - mn1);
        float rs0 = 0.f, rs1 = 0.f;
#pragma unroll
        for (int ni = 0; ni < 8; ni++) {
            float p00 = __expf(sacc[ni][0] - mn0);
            float p01 = __expf(sacc[ni][1] - mn0);
            float p10 = __expf(sacc[ni][2] - mn1);
            float p11 = __expf(sacc[ni][3] - mn1);
            rs0 += p00 + p01; rs1 += p10 + p11;
            pfrag[ni][0] = h2u(__floats2half2_rn(p00, p01));   // row gr
            pfrag[ni][1] = h2u(__floats2half2_rn(p10, p11));   // row gr+8
        }
        rs0 += __shfl_xor_sync(0xffffffffu, rs0, 1);
        rs0 += __shfl_xor_sync(0xffffffffu, rs0, 2);
        rs1 += __shfl_xor_sync(0xffffffffu, rs1, 1);
        rs1 += __shfl_xor_sync(0xffffffffu, rs1, 2);
        l0 = l0 * al0 + rs0; l1 = l1 * al1 + rs1;
        m0 = mn0; m1 = mn1;
#pragma unroll
        for (int ni = 0; ni < 8; ni++) {
            oacc[ni][0] *= al0; oacc[ni][1] *= al0;
            oacc[ni][2] *= al1; oacc[ni][3] *= al1;
        }

        // ---- O += P V : A-fragments straight from registers ----
#pragma unroll
        for (int ks = 0; ks < 4; ks++) {
            const uint32_t a0 = pfrag[2 * ks][0];
            const uint32_t a1 = pfrag[2 * ks][1];
            const uint32_t a2 = pfrag[2 * ks + 1][0];
            const uint32_t a3 = pfrag[2 * ks + 1][1];
#pragma unroll
            for (int a = 0; a < 4; a++) {
                const int kk_ = ks * 16 + (mat & 1) * 8 + mrow;
                const int d_  = a * 16 + (mat >> 1) * 8;
                uint32_t b0, b1, b2, b3;
                ldsm4t(b0, b1, b2, b3, Vsu + (uint32_t)(kk_ * KPITCH + d_) * 2);
                mma_f16(oacc[2 * a],     a0, a1, a2, a3, b0, b1);
                mma_f16(oacc[2 * a + 1], a0, a1, a2, a3, b2, b3);
            }
        }
    }

    // ---- write O (fp16) ----
    const float i0 = 1.0f / l0, i1 = 1.0f / l1;
    const size_t r0 = (rowbase + q0 + wr + gr) * (size_t)DM + hh * DH;
    const size_t r1 = r0 + 8 * DM;
#pragma unroll
    for (int ni = 0; ni < 8; ni++) {
        const int c = ni * 8 + 2 * tg;
        *reinterpret_cast<__half2*>(&O[r0 + c]) =
            __floats2half2_rn(oacc[ni][0] * i0, oacc[ni][1] * i0);
        *reinterpret_cast<__half2*>(&O[r1 + c]) =
            __floats2half2_rn(oacc[ni][2] * i1, oacc[ni][3] * i1);
    }
}

// ---------------- launcher ----------------
extern "C" void kernel_launch(void* const* d_in, const int* in_sizes, int n_in,
                              void* d_out, int out_size)
{
    const float* x     = (const float*)d_in[0];
    const float* ln1_g = (const float*)d_in[1];
    const float* ln1_b = (const float*)d_in[2];
    const float* w_qkv = (const float*)d_in[3];
    const float* w_out = (const float*)d_in[4];
    const float* b_out = (const float*)d_in[5];
    const float* ln2_g = (const float*)d_in[6];
    const float* ln2_b = (const float*)d_in[7];
    const float* w1    = (const float*)d_in[8];
    const float* b1    = (const float*)d_in[9];
    const float* w2    = (const float*)d_in[10];
    const float* b2    = (const float*)d_in[11];
    float* out = (float*)d_out;

    __half *h, *qkv, *o, *ff, *wc;
    float *x2;
    cudaGetSymbolAddress((void**)&h,   g_h);
    cudaGetSymbolAddress((void**)&qkv, g_qkv);
    cudaGetSymbolAddress((void**)&o,   g_o);
    cudaGetSymbolAddress((void**)&x2,  g_x2);
    cudaGetSymbolAddress((void**)&ff,  g_ff);
    cudaGetSymbolAddress((void**)&wc,  g_wc);

    __half* wqkv_t = wc;                       // [3072][1024]
    __half* wout_t = wqkv_t + DM * 3 * DM;     // [1024][1024]
    __half* w1_t   = wout_t + DM * DM;         // [4096][1024]
    __half* w2_t   = w1_t + DM * DFF;          // [1024][4096]

    cudaFuncSetAttribute(attn_kernel,
                         cudaFuncAttributeMaxDynamicSharedMemorySize, ATT_SMEM);
    cudaFuncSetAttribute(gemm_f16<0>,
                         cudaFuncAttributeMaxDynamicSharedMemorySize, GEMM_SMEM);
    cudaFuncSetAttribute(gemm_f16<1>,
                         cudaFuncAttributeMaxDynamicSharedMemorySize, GEMM_SMEM);
    cudaFuncSetAttribute(gemm_f16<2>,
                         cudaFuncAttributeMaxDynamicSharedMemorySize, GEMM_SMEM);

    // 0) all 4 weight transposes in ONE launch
    transpose_all_kernel<<<12288, dim3(32, 8)>>>(
        w_qkv, w_out, w1, w2, wqkv_t, wout_t, w1_t, w2_t);

    // 1) h = LN1(x)
    ln_kernel<<<NTOK, 256>>>(x, ln1_g, ln1_b, h);
    // 2) qkv = h @ w_qkv
    gemm_f16<0><<<dim3(3 * DM / 128, NTOK / 128), 256, GEMM_SMEM>>>(
        h, wqkv_t, nullptr, nullptr, nullptr, qkv, NTOK, 3 * DM, DM);
    // 3) o = causal_attention(qkv)
    attn_kernel<<<dim3(TSEQ / 128, 4 * NH), 256, ATT_SMEM>>>(qkv, o);
    // 4) x2 = x + o @ w_out + b_out  (fp32 out)
    gemm_f16<2><<<dim3(DM / 128, NTOK / 128), 256, GEMM_SMEM>>>(
        o, wout_t, b_out, x, x2, nullptr, NTOK, DM, DM);
    // 5) h = LN2(x2)
    ln_kernel<<<NTOK, 256>>>(x2, ln2_g, ln2_b, h);
    // 6) ff = gelu(h @ w1 + b1)
    gemm_f16<1><<<dim3(DFF / 128, NTOK / 128), 256, GEMM_SMEM>>>(
        h, w1_t, b1, nullptr, nullptr, ff, NTOK, DFF, DM);
    // 7) out = x2 + ff @ w2 + b2  (fp32 out)
    gemm_f16<2><<<dim3(DM / 128, NTOK / 128), 256, GEMM_SMEM>>>(
        ff, w2_t, b2, x2, out, nullptr, NTOK, DM, DFF);
}

// round 15
// speedup vs baseline: 1.0956x; 1.0076x over previous
#include <cuda_runtime.h>
#include <cuda_fp16.h>
#include <math.h>
#include <stdint.h>

#define NTOK   8192      // B*T
#define DM     1024
#define DFF    4096
#define TSEQ   2048
#define NH     16
#define DH     64

// ---------------- scratch (static device globals; no allocation) ----------------
__device__ __half g_h  [NTOK * DM];       // LN output (fp16)
__device__ __half g_qkv[NTOK * 3 * DM];   // qkv projections (fp16)
__device__ __half g_o  [NTOK * DM];       // attention output (fp16)
__device__ float  g_x2 [NTOK * DM];       // residual after attention (fp32)
__device__ __half g_ff [NTOK * DFF];      // gelu output (fp16)
__device__ __half g_wc [DM*3*DM + DM*DM + DM*DFF + DFF*DM]; // fp16 weights, [n][k]

// ---------------- fused weight transpose + fp16 convert (all 4 weights) ----------
__global__ void __launch_bounds__(256) transpose_all_kernel(
    const float* __restrict__ w0, const float* __restrict__ w1,
    const float* __restrict__ w2, const float* __restrict__ w3,
    __half* __restrict__ d0, __half* __restrict__ d1,
    __half* __restrict__ d2, __half* __restrict__ d3)
{
    __shared__ float tile[32][33];
    const int bid = blockIdx.x;
    const float* in; __half* out; int K, N, nx, local;
    if (bid < 3072)      { in = w0; out = d0; K = 1024; N = 3072; nx = 96;  local = bid; }
    else if (bid < 4096) { in = w1; out = d1; K = 1024; N = 1024; nx = 32;  local = bid - 3072; }
    else if (bid < 8192) { in = w2; out = d2; K = 1024; N = 4096; nx = 128; local = bid - 4096; }
    else                 { in = w3; out = d3; K = 4096; N = 1024; nx = 32;  local = bid - 8192; }
    const int n0 = (local % nx) * 32, k0 = (local / nx) * 32;
    const int tx = threadIdx.x, ty = threadIdx.y;   // block (32, 8)
#pragma unroll
    for (int i = 0; i < 4; i++)
        tile[ty + i * 8][tx] = in[(size_t)(k0 + ty + i * 8) * N + n0 + tx];
    __syncthreads();
#pragma unroll
    for (int i = 0; i < 4; i++)
        out[(size_t)(n0 + ty + i * 8) * K + k0 + tx] =
            __float2half_rn(tile[tx][ty + i * 8]);
}

// ---------------- LayerNorm: fp32 in -> fp16 out (vectorized) ----------------
__global__ void __launch_bounds__(256) ln_kernel(
    const float* __restrict__ x, const float* __restrict__ g,
    const float* __restrict__ b, __half* __restrict__ out)
{
    const int row = blockIdx.x;
    const int t4 = threadIdx.x * 4;
    const float4 v = *reinterpret_cast<const float4*>(x + (size_t)row * DM + t4);
    float s  = v.x + v.y + v.z + v.w;
    float s2 = v.x * v.x + v.y * v.y + v.z * v.z + v.w * v.w;
#pragma unroll
    for (int off = 16; off; off >>= 1) {
        s  += __shfl_xor_sync(0xffffffffu, s,  off);
        s2 += __shfl_xor_sync(0xffffffffu, s2, off);
    }
    __shared__ float ss[8], ss2[8];
    const int w = threadIdx.x >> 5, ln = threadIdx.x & 31;
    if (ln == 0) { ss[w] = s; ss2[w] = s2; }
    __syncthreads();
    s = 0.f; s2 = 0.f;
#pragma unroll
    for (int i = 0; i < 8; i++) { s += ss[i]; s2 += ss2[i]; }
    const float mean = s * (1.0f / DM);
    const float var  = s2 * (1.0f / DM) - mean * mean;
    const float rstd = rsqrtf(var + 1e-5f);
    const float4 gv = *reinterpret_cast<const float4*>(g + t4);
    const float4 bv = *reinterpret_cast<const float4*>(b + t4);
    __half2 h01 = __floats2half2_rn((v.x - mean) * rstd * gv.x + bv.x,
                                    (v.y - mean) * rstd * gv.y + bv.y);
    __half2 h23 = __floats2half2_rn((v.z - mean) * rstd * gv.z + bv.z,
                                    (v.w - mean) * rstd * gv.w + bv.w);
    __half2* orow = reinterpret_cast<__half2*>(out + (size_t)row * DM + t4);
    orow[0] = h01;
    orow[1] = h23;
}

// ================ fp16 tensor-core GEMM (R7-exact: 3-stage, 128x128) ================
__device__ __forceinline__ float gelu_exact(float x) {
    return 0.5f * x * (1.0f + erff(x * 0.70710678118654752f));
}
__device__ __forceinline__ void ldsm4(uint32_t& r0, uint32_t& r1,
                                      uint32_t& r2, uint32_t& r3, uint32_t addr) {
    asm volatile("ldmatrix.sync.aligned.m8n8.x4.shared.b16 {%0,%1,%2,%3}, [%4];\n"
                 : "=r"(r0), "=r"(r1), "=r"(r2), "=r"(r3) : "r"(addr));
}
__device__ __forceinline__ void ldsm4t(uint32_t& r0, uint32_t& r1,
                                       uint32_t& r2, uint32_t& r3, uint32_t addr) {
    asm volatile("ldmatrix.sync.aligned.m8n8.x4.trans.shared.b16 {%0,%1,%2,%3}, [%4];\n"
                 : "=r"(r0), "=r"(r1), "=r"(r2), "=r"(r3) : "r"(addr));
}
__device__ __forceinline__ void mma_f16(float* c,
    uint32_t a0, uint32_t a1, uint32_t a2, uint32_t a3, uint32_t b0, uint32_t b1) {
    asm volatile(
        "mma.sync.aligned.m16n8k16.row.col.f32.f16.f16.f32 "
        "{%0,%1,%2,%3}, {%4,%5,%6,%7}, {%8,%9}, {%0,%1,%2,%3};\n"
        : "+f"(c[0]), "+f"(c[1]), "+f"(c[2]), "+f"(c[3])
        : "r"(a0), "r"(a1), "r"(a2), "r"(a3), "r"(b0), "r"(b1));
}
__device__ __forceinline__ void cp16(__half* dst, const __half* src) {
    uint32_t d = (uint32_t)__cvta_generic_to_shared(dst);
    asm volatile("cp.async.cg.shared.global [%0], [%1], 16;\n" :: "r"(d), "l"(src));
}
__device__ __forceinline__ uint32_t h2u(__half2 h) {
    uint32_t u;
    asm("mov.b32 %0, %1;" : "=r"(u) : "r"(*reinterpret_cast<uint32_t*>(&h)));
    return u;
}

#define GPITCH 40                       // halves per smem row (64B data + 16B pad)
#define G_TILE (128 * GPITCH)           // halves per operand tile
#define G_STAGE (2 * G_TILE)            // halves per stage (A + B)
#define GEMM_SMEM (3 * G_STAGE * 2)     // bytes (= 61440)

template<int EPI>
__global__ void __launch_bounds__(256) gemm_f16(
    const __half* __restrict__ A, const __half* __restrict__ Bt,
    const float* __restrict__ bias, const float* __restrict__ res,
    float* __restrict__ Cf, __half* __restrict__ Ch, int M, int N, int K)
{
    extern __shared__ __half smh[];
    const int tid  = threadIdx.x;
    const int lane = tid & 31, wid = tid >> 5;
    const int bm = blockIdx.y * 128, bn = blockIdx.x * 128;
    const int wm = (wid >> 2) * 64;
    const int wn = (wid & 3) * 32;
    const int gr = lane >> 2, tg = lane & 3;

    const uint32_t smem_u32 = (uint32_t)__cvta_generic_to_shared(smh);
    const int mat  = lane >> 3;
    const int mrow = lane & 7;

    float acc[4][4][4];
#pragma unroll
    for (int i = 0; i < 4; i++)
#pragma unroll
        for (int j = 0; j < 4; j++)
#pragma unroll
            for (int r = 0; r < 4; r++) acc[i][j][r] = 0.f;

    const int KT = K >> 5;

    auto issue = [&](int kt) {
        const int stg = kt % 3;
        const int k0 = kt << 5;
        __half* As = smh + stg * G_STAGE;
        __half* Bs = As + G_TILE;
#pragma unroll
        for (int i = 0; i < 2; i++) {
            const int c = tid + i * 256;
            const int row = c >> 2, kc = (c & 3) * 8;
            cp16(As + row * GPITCH + kc, A  + (size_t)(bm + row) * K + k0 + kc);
        }
#pragma unroll
        for (int i = 0; i < 2; i++) {
            const int c = tid + i * 256;
            const int row = c >> 2, kc = (c & 3) * 8;
            cp16(Bs + row * GPITCH + kc, Bt + (size_t)(bn + row) * K + k0 + kc);
        }
    };

    issue(0);
    asm volatile("cp.async.commit_group;\n");
    if (KT > 1) { issue(1); asm volatile("cp.async.commit_group;\n"); }

    for (int kt = 0; kt < KT; kt++) {
        const int cur = kt % 3;
        if (kt + 1 < KT) asm volatile("cp.async.wait_group 1;\n");
        else             asm volatile("cp.async.wait_group 0;\n");
        __syncthreads();
        if (kt + 2 < KT) { issue(kt + 2); asm volatile("cp.async.commit_group;\n"); }

        const uint32_t As_u = smem_u32 + (cur * G_STAGE) * 2;
        const uint32_t Bs_u = As_u + G_TILE * 2;

#pragma unroll
        for (int ks = 0; ks < 2; ks++) {
            uint32_t rb[4][2];
#pragma unroll
            for (int a = 0; a < 2; a++) {
                const int n_ = wn + a * 16 + (mat >> 1) * 8 + mrow;
                const int k_ = ks * 16 + (mat & 1) * 8;
                uint32_t r0, r1, r2, r3;
                ldsm4(r0, r1, r2, r3, Bs_u + (uint32_t)(n_ * GPITCH + k_) * 2);
                rb[2 * a][0] = r0; rb[2 * a][1] = r1;
                rb[2 * a + 1][0] = r2; rb[2 * a + 1][1] = r3;
            }
            uint32_t ra[4][4];
#pragma unroll
            for (int mi = 0; mi < 4; mi++) {
                const int m_ = wm + mi * 16 + ((mat & 1) ? 8 : 0) + mrow;
                const int k_ = ks * 16 + ((mat >> 1) ? 8 : 0);
                ldsm4(ra[mi][0], ra[mi][1], ra[mi][2], ra[mi][3],
                      As_u + (uint32_t)(m_ * GPITCH + k_) * 2);
            }
#pragma unroll
            for (int mi = 0; mi < 4; mi++)
#pragma unroll
                for (int ni = 0; ni < 4; ni++)
                    mma_f16(acc[mi][ni], ra[mi][0], ra[mi][1], ra[mi][2], ra[mi][3],
                            rb[ni][0], rb[ni][1]);
        }
        __syncthreads();
    }

    // ---- epilogue ----
#pragma unroll
    for (int mi = 0; mi < 4; mi++) {
        const int row0 = bm + wm + mi * 16 + gr;
        const int row1 = row0 + 8;
#pragma unroll
        for (int ni = 0; ni < 4; ni++) {
            const int col = bn + wn + ni * 8 + 2 * tg;
            float v0 = acc[mi][ni][0], v1 = acc[mi][ni][1];
            float v2 = acc[mi][ni][2], v3 = acc[mi][ni][3];
            if (EPI == 1) {
                const float bb0 = bias[col], bb1 = bias[col + 1];
                v0 = gelu_exact(v0 + bb0); v1 = gelu_exact(v1 + bb1);
                v2 = gelu_exact(v2 + bb0); v3 = gelu_exact(v3 + bb1);
            }
            if (EPI == 2) {
                const float bb0 = bias[col], bb1 = bias[col + 1];
                const float2 r0 = *reinterpret_cast<const float2*>(&res[(size_t)row0 * N + col]);
                const float2 r1 = *reinterpret_cast<const float2*>(&res[(size_t)row1 * N + col]);
                v0 += bb0 + r0.x; v1 += bb1 + r0.y;
                v2 += bb0 + r1.x; v3 += bb1 + r1.y;
                *reinterpret_cast<float2*>(&Cf[(size_t)row0 * N + col]) = make_float2(v0, v1);
                *reinterpret_cast<float2*>(&Cf[(size_t)row1 * N + col]) = make_float2(v2, v3);
            } else {
                *reinterpret_cast<__half2*>(&Ch[(size_t)row0 * N + col]) =
                    __floats2half2_rn(v0, v1);
                *reinterpret_cast<__half2*>(&Ch[(size_t)row1 * N + col]) =
                    __floats2half2_rn(v2, v3);
            }
        }
    }
}

// ============ fp16 tensor-core causal flash attention ============
// 3-stage K/V cp.async pipeline, ONE barrier per K-iteration, register-resident P,
// heavy-first scheduling.
#define QPITCH 72
#define KPITCH 72
#define KV_STAGE (64 * KPITCH)          // halves per K (or V) stage
#define ATT_SMEM ((128*QPITCH + 3*KV_STAGE + 3*KV_STAGE) * 2)

__global__ void __launch_bounds__(256) attn_kernel(
    const __half* __restrict__ qkv, __half* __restrict__ O)
{
    const int qt = gridDim.x - 1 - blockIdx.x;   // heavy tiles scheduled first
    const int bh = blockIdx.y;
    const int bb = bh >> 4, hh = bh & 15;
    const int tid = threadIdx.x;
    const int lane = tid & 31, wid = tid >> 5;
    const int gr = lane >> 2, tg = lane & 3;
    const int mat = lane >> 3, mrow = lane & 7;
    const size_t rowbase = (size_t)bb * TSEQ;
    const int qoff = hh * DH;
    const int koff = DM + hh * DH;
    const int voff = 2 * DM + hh * DH;
    const int q0 = qt * 128;
    const int wr = wid * 16;

    extern __shared__ __half smh[];
    __half* Qs = smh;                           // [128][QPITCH]
    __half* Ks = Qs + 128 * QPITCH;             // 3 x [64][KPITCH]
    __half* Vs = Ks + 3 * KV_STAGE;             // 3 x [64][KPITCH]
    const uint32_t Qs_u = (uint32_t)__cvta_generic_to_shared(Qs);
    const uint32_t Ks_u = (uint32_t)__cvta_generic_to_shared(Ks);
    const uint32_t Vs_u = (uint32_t)__cvta_generic_to_shared(Vs);

    // load Q tile (scale by 1/8, exact)
    {
        const __half2 sc = __floats2half2_rn(0.125f, 0.125f);
        for (int e = tid; e < 128 * 32; e += 256) {
            const int r = e >> 5, d2 = e & 31;
            __half2 v = *reinterpret_cast<const __half2*>(
                &qkv[(rowbase + q0 + r) * (size_t)(3 * DM) + qoff + 2 * d2]);
            *reinterpret_cast<__half2*>(&Qs[r * QPITCH + 2 * d2]) = __hmul2(v, sc);
        }
    }

    // async K/V stage loader (3-stage ring)
    auto issue_kv = [&](int kt) {
        const int s = kt % 3;
        const int k0 = kt * 64;
        __half* Kd = Ks + s * KV_STAGE;
        __half* Vd = Vs + s * KV_STAGE;
#pragma unroll
        for (int i = 0; i < 4; i++) {
            const int c = tid + i * 256;          // 0..1023
            const int sel = c >> 9;               // 0 = K, 1 = V
            const int r = (c >> 3) & 63;
            const int kc = (c & 7) * 8;
            const size_t base = (rowbase + k0 + r) * (size_t)(3 * DM);
            if (sel == 0) cp16(Kd + r * KPITCH + kc, qkv + base + koff + kc);
            else          cp16(Vd + r * KPITCH + kc, qkv + base + voff + kc);
        }
    };

    float oacc[8][4];
    float sacc[8][4];
    uint32_t pfrag[8][2];               // P as half2 fragments, register-resident
#pragma unroll
    for (int i = 0; i < 8; i++)
#pragma unroll
        for (int r = 0; r < 4; r++) oacc[i][r] = 0.f;
    float m0 = -1e30f, m1 = -1e30f, l0 = 0.f, l1 = 0.f;

    const int kt_max = 2 * qt + 1;
    issue_kv(0);
    asm volatile("cp.async.commit_group;\n");
    if (kt_max >= 1) { issue_kv(1); asm volatile("cp.async.commit_group;\n"); }

    for (int kt = 0; kt <= kt_max; kt++) {
        if (kt + 1 <= kt_max) asm volatile("cp.async.wait_group 1;\n");
        else                  asm volatile("cp.async.wait_group 0;\n");
        __syncthreads();   // stage kt visible; proves stage (kt-1)%3 reads finished
        if (kt + 2 <= kt_max) {
            issue_kv(kt + 2);
            asm volatile("cp.async.commit_group;\n");
        }

        const uint32_t Ksu = Ks_u + (uint32_t)((kt % 3) * KV_STAGE) * 2;
        const uint32_t Vsu = Vs_u + (uint32_t)((kt % 3) * KV_STAGE) * 2;
        const int k0 = kt * 64;

        // ---- S = Q K^T ----
#pragma unroll
        for (int i = 0; i < 8; i++)
#pragma unroll
            for (int r = 0; r < 4; r++) sacc[i][r] = 0.f;
#pragma unroll
        for (int ks = 0; ks < 4; ks++) {
            uint32_t a0, a1, a2, a3;
            {
                const int m_ = wr + ((mat & 1) ? 8 : 0) + mrow;
                const int k_ = ks * 16 + ((mat >> 1) ? 8 : 0);
                ldsm4(a0, a1, a2, a3, Qs_u + (uint32_t)(m_ * QPITCH + k_) * 2);
            }
#pragma unroll
            for (int a = 0; a < 4; a++) {
                const int n_ = a * 16 + (mat >> 1) * 8 + mrow;
                const int d_ = ks * 16 + (mat & 1) * 8;
                uint32_t b0, b1, b2, b3;
                ldsm4(b0, b1, b2, b3, Ksu + (uint32_t)(n_ * KPITCH + d_) * 2);
                mma_f16(sacc[2 * a],     a0, a1, a2, a3, b0, b1);
                mma_f16(sacc[2 * a + 1], a0, a1, a2, a3, b2, b3);
            }
        }

        // ---- causal mask ----
        const int row_g0 = q0 + wr + gr, row_g1 = row_g0 + 8;
        if (kt >= 2 * qt) {
#pragma unroll
            for (int ni = 0; ni < 8; ni++) {
                const int c0 = k0 + ni * 8 + 2 * tg, c1 = c0 + 1;
                if (c0 > row_g0) sacc[ni][0] = -1e30f;
                if (c1 > row_g0) sacc[ni][1] = -1e30f;
                if (c0 > row_g1) sacc[ni][2] = -1e30f;
                if (c1 > row_g1) sacc[ni][3] = -1e30f;
            }
        }

        // ---- online softmax; P -> half2 register fragments ----
        float mx0 = -1e30f, mx1 = -1e30f;
#pragma unroll
        for (int ni = 0; ni < 8; ni++) {
            mx0 = fmaxf(mx0, fmaxf(sacc[ni][0], sacc[ni][1]));
            mx1 = fmaxf(mx1, fmaxf(sacc[ni][2], sacc[ni][3]));
        }
        mx0 = fmaxf(mx0, __shfl_xor_sync(0xffffffffu, mx0, 1));
        mx0 = fmaxf(mx0, __shfl_xor_sync(0xffffffffu, mx0, 2));
        mx1 = fmaxf(mx1, __shfl_xor_sync(0xffffffffu, mx1, 1));
        mx1 = fmaxf(mx1, __shfl_xor_sync(0xffffffffu, mx1, 2));
        const float mn0 = fmaxf(m0, mx0), mn1 = fmaxf(m1, mx1);
        const float al0 = __expf(m0 - mn0), al1 = __expf(m1 - mn1);
        float rs0 = 0.f, rs1 = 0.f;
#pragma unroll
        for (int ni = 0; ni < 8; ni++) {
            float p00 = __expf(sacc[ni][0] - mn0);
            float p01 = __expf(sacc[ni][1] - mn0);
            float p10 = __expf(sacc[ni][2] - mn1);
            float p11 = __expf(sacc[ni][3] - mn1);
            rs0 += p00 + p01; rs1 += p10 + p11;
            pfrag[ni][0] = h2u(__floats2half2_rn(p00, p01));   // row gr
            pfrag[ni][1] = h2u(__floats2half2_rn(p10, p11));   // row gr+8
        }
        rs0 += __shfl_xor_sync(0xffffffffu, rs0, 1);
        rs0 += __shfl_xor_sync(0xffffffffu, rs0, 2);
        rs1 += __shfl_xor_sync(0xffffffffu, rs1, 1);
        rs1 += __shfl_xor_sync(0xffffffffu, rs1, 2);
        l0 = l0 * al0 + rs0; l1 = l1 * al1 + rs1;
        m0 = mn0; m1 = mn1;
#pragma unroll
        for (int ni = 0; ni < 8; ni++) {
            oacc[ni][0] *= al0; oacc[ni][1] *= al0;
            oacc[ni][2] *= al1; oacc[ni][3] *= al1;
        }

        // ---- O += P V : A-fragments straight from registers ----
#pragma unroll
        for (int ks = 0; ks < 4; ks++) {
            const uint32_t a0 = pfrag[2 * ks][0];
            const uint32_t a1 = pfrag[2 * ks][1];
            const uint32_t a2 = pfrag[2 * ks + 1][0];
            const uint32_t a3 = pfrag[2 * ks + 1][1];
#pragma unroll
            for (int a = 0; a < 4; a++) {
                const int kk_ = ks * 16 + (mat & 1) * 8 + mrow;
                const int d_  = a * 16 + (mat >> 1) * 8;
                uint32_t b0, b1, b2, b3;
                ldsm4t(b0, b1, b2, b3, Vsu + (uint32_t)(kk_ * KPITCH + d_) * 2);
                mma_f16(oacc[2 * a],     a0, a1, a2, a3, b0, b1);
                mma_f16(oacc[2 * a + 1], a0, a1, a2, a3, b2, b3);
            }
        }
        // no trailing barrier: next iteration's barrier provides the ordering
    }

    // ---- write O (fp16) ----
    const float i0 = 1.0f / l0, i1 = 1.0f / l1;
    const size_t r0 = (rowbase + q0 + wr + gr) * (size_t)DM + hh * DH;
    const size_t r1 = r0 + 8 * DM;
#pragma unroll
    for (int ni = 0; ni < 8; ni++) {
        const int c = ni * 8 + 2 * tg;
        *reinterpret_cast<__half2*>(&O[r0 + c]) =
            __floats2half2_rn(oacc[ni][0] * i0, oacc[ni][1] * i0);
        *reinterpret_cast<__half2*>(&O[r1 + c]) =
            __floats2half2_rn(oacc[ni][2] * i1, oacc[ni][3] * i1);
    }
}

// ---------------- launcher ----------------
extern "C" void kernel_launch(void* const* d_in, const int* in_sizes, int n_in,
                              void* d_out, int out_size)
{
    const float* x     = (const float*)d_in[0];
    const float* ln1_g = (const float*)d_in[1];
    const float* ln1_b = (const float*)d_in[2];
    const float* w_qkv = (const float*)d_in[3];
    const float* w_out = (const float*)d_in[4];
    const float* b_out = (const float*)d_in[5];
    const float* ln2_g = (const float*)d_in[6];
    const float* ln2_b = (const float*)d_in[7];
    const float* w1    = (const float*)d_in[8];
    const float* b1    = (const float*)d_in[9];
    const float* w2    = (const float*)d_in[10];
    const float* b2    = (const float*)d_in[11];
    float* out = (float*)d_out;

    __half *h, *qkv, *o, *ff, *wc;
    float *x2;
    cudaGetSymbolAddress((void**)&h,   g_h);
    cudaGetSymbolAddress((void**)&qkv, g_qkv);
    cudaGetSymbolAddress((void**)&o,   g_o);
    cudaGetSymbolAddress((void**)&x2,  g_x2);
    cudaGetSymbolAddress((void**)&ff,  g_ff);
    cudaGetSymbolAddress((void**)&wc,  g_wc);

    __half* wqkv_t = wc;                       // [3072][1024]
    __half* wout_t = wqkv_t + DM * 3 * DM;     // [1024][1024]
    __half* w1_t   = wout_t + DM * DM;         // [4096][1024]
    __half* w2_t   = w1_t + DM * DFF;          // [1024][4096]

    cudaFuncSetAttribute(attn_kernel,
                         cudaFuncAttributeMaxDynamicSharedMemorySize, ATT_SMEM);
    cudaFuncSetAttribute(gemm_f16<0>,
                         cudaFuncAttributeMaxDynamicSharedMemorySize, GEMM_SMEM);
    cudaFuncSetAttribute(gemm_f16<1>,
                         cudaFuncAttributeMaxDynamicSharedMemorySize, GEMM_SMEM);
    cudaFuncSetAttribute(gemm_f16<2>,
                         cudaFuncAttributeMaxDynamicSharedMemorySize, GEMM_SMEM);

    // 0) all 4 weight transposes in ONE launch
    transpose_all_kernel<<<12288, dim3(32, 8)>>>(
        w_qkv, w_out, w1, w2, wqkv_t, wout_t, w1_t, w2_t);

    // 1) h = LN1(x)
    ln_kernel<<<NTOK, 256>>>(x, ln1_g, ln1_b, h);
    // 2) qkv = h @ w_qkv
    gemm_f16<0><<<dim3(3 * DM / 128, NTOK / 128), 256, GEMM_SMEM>>>(
        h, wqkv_t, nullptr, nullptr, nullptr, qkv, NTOK, 3 * DM, DM);
    // 3) o = causal_attention(qkv)
    attn_kernel<<<dim3(TSEQ / 128, 4 * NH), 256, ATT_SMEM>>>(qkv, o);
    // 4) x2 = x + o @ w_out + b_out  (fp32 out)
    gemm_f16<2><<<dim3(DM / 128, NTOK / 128), 256, GEMM_SMEM>>>(
        o, wout_t, b_out, x, x2, nullptr, NTOK, DM, DM);
    // 5) h = LN2(x2)
    ln_kernel<<<NTOK, 256>>>(x2, ln2_g, ln2_b, h);
    // 6) ff = gelu(h @ w1 + b1)
    gemm_f16<1><<<dim3(DFF / 128, NTOK / 128), 256, GEMM_SMEM>>>(
        h, w1_t, b1, nullptr, nullptr, ff, NTOK, DFF, DM);
    // 7) out = x2 + ff @ w2 + b2  (fp32 out)
    gemm_f16<2><<<dim3(DM / 128, NTOK / 128), 256, GEMM_SMEM>>>(
        ff, w2_t, b2, x2, out, nullptr, NTOK, DM, DFF);
}

// round 16
// speedup vs baseline: 1.0962x; 1.0005x over previous
#include <cuda_runtime.h>
#include <cuda_fp16.h>
#include <math.h>
#include <stdint.h>

#define NTOK   8192      // B*T
#define DM     1024
#define DFF    4096
#define TSEQ   2048
#define NH     16
#define DH     64

// ---------------- scratch (static device globals; no allocation) ----------------
__device__ __half g_h  [NTOK * DM];       // LN output (fp16)
__device__ __half g_qkv[NTOK * 3 * DM];   // qkv projections (fp16)
__device__ __half g_o  [NTOK * DM];       // attention output (fp16)
__device__ float  g_x2 [NTOK * DM];       // residual after attention (fp32)
__device__ __half g_ff [NTOK * DFF];      // gelu output (fp16)
__device__ __half g_wc [DM*3*DM + DM*DM + DM*DFF + DFF*DM]; // fp16 weights, [n][k]

// ---------------- fused weight transpose + fp16 convert (all 4 weights) ----------
__global__ void __launch_bounds__(256) transpose_all_kernel(
    const float* __restrict__ w0, const float* __restrict__ w1,
    const float* __restrict__ w2, const float* __restrict__ w3,
    __half* __restrict__ d0, __half* __restrict__ d1,
    __half* __restrict__ d2, __half* __restrict__ d3)
{
    __shared__ float tile[32][33];
    const int bid = blockIdx.x;
    const float* in; __half* out; int K, N, nx, local;
    if (bid < 3072)      { in = w0; out = d0; K = 1024; N = 3072; nx = 96;  local = bid; }
    else if (bid < 4096) { in = w1; out = d1; K = 1024; N = 1024; nx = 32;  local = bid - 3072; }
    else if (bid < 8192) { in = w2; out = d2; K = 1024; N = 4096; nx = 128; local = bid - 4096; }
    else                 { in = w3; out = d3; K = 4096; N = 1024; nx = 32;  local = bid - 8192; }
    const int n0 = (local % nx) * 32, k0 = (local / nx) * 32;
    const int tx = threadIdx.x, ty = threadIdx.y;   // block (32, 8)
#pragma unroll
    for (int i = 0; i < 4; i++)
        tile[ty + i * 8][tx] = in[(size_t)(k0 + ty + i * 8) * N + n0 + tx];
    __syncthreads();
#pragma unroll
    for (int i = 0; i < 4; i++)
        out[(size_t)(n0 + ty + i * 8) * K + k0 + tx] =
            __float2half_rn(tile[tx][ty + i * 8]);
}

// ---------------- LayerNorm: fp32 in -> fp16 out (vectorized) ----------------
__global__ void __launch_bounds__(256) ln_kernel(
    const float* __restrict__ x, const float* __restrict__ g,
    const float* __restrict__ b, __half* __restrict__ out)
{
    const int row = blockIdx.x;
    const int t4 = threadIdx.x * 4;
    const float4 v = *reinterpret_cast<const float4*>(x + (size_t)row * DM + t4);
    float s  = v.x + v.y + v.z + v.w;
    float s2 = v.x * v.x + v.y * v.y + v.z * v.z + v.w * v.w;
#pragma unroll
    for (int off = 16; off; off >>= 1) {
        s  += __shfl_xor_sync(0xffffffffu, s,  off);
        s2 += __shfl_xor_sync(0xffffffffu, s2, off);
    }
    __shared__ float ss[8], ss2[8];
    const int w = threadIdx.x >> 5, ln = threadIdx.x & 31;
    if (ln == 0) { ss[w] = s; ss2[w] = s2; }
    __syncthreads();
    s = 0.f; s2 = 0.f;
#pragma unroll
    for (int i = 0; i < 8; i++) { s += ss[i]; s2 += ss2[i]; }
    const float mean = s * (1.0f / DM);
    const float var  = s2 * (1.0f / DM) - mean * mean;
    const float rstd = rsqrtf(var + 1e-5f);
    const float4 gv = *reinterpret_cast<const float4*>(g + t4);
    const float4 bv = *reinterpret_cast<const float4*>(b + t4);
    __half2 h01 = __floats2half2_rn((v.x - mean) * rstd * gv.x + bv.x,
                                    (v.y - mean) * rstd * gv.y + bv.y);
    __half2 h23 = __floats2half2_rn((v.z - mean) * rstd * gv.z + bv.z,
                                    (v.w - mean) * rstd * gv.w + bv.w);
    __half2* orow = reinterpret_cast<__half2*>(out + (size_t)row * DM + t4);
    orow[0] = h01;
    orow[1] = h23;
}

// ================ fp16 tensor-core GEMM (R7-exact: 3-stage, 128x128) ================
__device__ __forceinline__ float gelu_exact(float x) {
    return 0.5f * x * (1.0f + erff(x * 0.70710678118654752f));
}
__device__ __forceinline__ void ldsm4(uint32_t& r0, uint32_t& r1,
                                      uint32_t& r2, uint32_t& r3, uint32_t addr) {
    asm volatile("ldmatrix.sync.aligned.m8n8.x4.shared.b16 {%0,%1,%2,%3}, [%4];\n"
                 : "=r"(r0), "=r"(r1), "=r"(r2), "=r"(r3) : "r"(addr));
}
__device__ __forceinline__ void ldsm4t(uint32_t& r0, uint32_t& r1,
                                       uint32_t& r2, uint32_t& r3, uint32_t addr) {
    asm volatile("ldmatrix.sync.aligned.m8n8.x4.trans.shared.b16 {%0,%1,%2,%3}, [%4];\n"
                 : "=r"(r0), "=r"(r1), "=r"(r2), "=r"(r3) : "r"(addr));
}
__device__ __forceinline__ void mma_f16(float* c,
    uint32_t a0, uint32_t a1, uint32_t a2, uint32_t a3, uint32_t b0, uint32_t b1) {
    asm volatile(
        "mma.sync.aligned.m16n8k16.row.col.f32.f16.f16.f32 "
        "{%0,%1,%2,%3}, {%4,%5,%6,%7}, {%8,%9}, {%0,%1,%2,%3};\n"
        : "+f"(c[0]), "+f"(c[1]), "+f"(c[2]), "+f"(c[3])
        : "r"(a0), "r"(a1), "r"(a2), "r"(a3), "r"(b0), "r"(b1));
}
__device__ __forceinline__ void cp16(__half* dst, const __half* src) {
    uint32_t d = (uint32_t)__cvta_generic_to_shared(dst);
    asm volatile("cp.async.cg.shared.global [%0], [%1], 16;\n" :: "r"(d), "l"(src));
}
__device__ __forceinline__ uint32_t h2u(__half2 h) {
    uint32_t u;
    asm("mov.b32 %0, %1;" : "=r"(u) : "r"(*reinterpret_cast<uint32_t*>(&h)));
    return u;
}

#define GPITCH 40                       // halves per smem row (64B data + 16B pad)
#define G_TILE (128 * GPITCH)           // halves per operand tile
#define G_STAGE (2 * G_TILE)            // halves per stage (A + B)
#define GEMM_SMEM (3 * G_STAGE * 2)     // bytes (= 61440)

template<int EPI>
__global__ void __launch_bounds__(256) gemm_f16(
    const __half* __restrict__ A, const __half* __restrict__ Bt,
    const float* __restrict__ bias, const float* __restrict__ res,
    float* __restrict__ Cf, __half* __restrict__ Ch, int M, int N, int K)
{
    extern __shared__ __half smh[];
    const int tid  = threadIdx.x;
    const int lane = tid & 31, wid = tid >> 5;
    const int bm = blockIdx.y * 128, bn = blockIdx.x * 128;
    const int wm = (wid >> 2) * 64;
    const int wn = (wid & 3) * 32;
    const int gr = lane >> 2, tg = lane & 3;

    const uint32_t smem_u32 = (uint32_t)__cvta_generic_to_shared(smh);
    const int mat  = lane >> 3;
    const int mrow = lane & 7;

    float acc[4][4][4];
#pragma unroll
    for (int i = 0; i < 4; i++)
#pragma unroll
        for (int j = 0; j < 4; j++)
#pragma unroll
            for (int r = 0; r < 4; r++) acc[i][j][r] = 0.f;

    const int KT = K >> 5;

    auto issue = [&](int kt) {
        const int stg = kt % 3;
        const int k0 = kt << 5;
        __half* As = smh + stg * G_STAGE;
        __half* Bs = As + G_TILE;
#pragma unroll
        for (int i = 0; i < 2; i++) {
            const int c = tid + i * 256;
            const int row = c >> 2, kc = (c & 3) * 8;
            cp16(As + row * GPITCH + kc, A  + (size_t)(bm + row) * K + k0 + kc);
        }
#pragma unroll
        for (int i = 0; i < 2; i++) {
            const int c = tid + i * 256;
            const int row = c >> 2, kc = (c & 3) * 8;
            cp16(Bs + row * GPITCH + kc, Bt + (size_t)(bn + row) * K + k0 + kc);
        }
    };

    issue(0);
    asm volatile("cp.async.commit_group;\n");
    if (KT > 1) { issue(1); asm volatile("cp.async.commit_group;\n"); }

    for (int kt = 0; kt < KT; kt++) {
        const int cur = kt % 3;
        if (kt + 1 < KT) asm volatile("cp.async.wait_group 1;\n");
        else             asm volatile("cp.async.wait_group 0;\n");
        __syncthreads();
        if (kt + 2 < KT) { issue(kt + 2); asm volatile("cp.async.commit_group;\n"); }

        const uint32_t As_u = smem_u32 + (cur * G_STAGE) * 2;
        const uint32_t Bs_u = As_u + G_TILE * 2;

#pragma unroll
        for (int ks = 0; ks < 2; ks++) {
            uint32_t rb[4][2];
#pragma unroll
            for (int a = 0; a < 2; a++) {
                const int n_ = wn + a * 16 + (mat >> 1) * 8 + mrow;
                const int k_ = ks * 16 + (mat & 1) * 8;
                uint32_t r0, r1, r2, r3;
                ldsm4(r0, r1, r2, r3, Bs_u + (uint32_t)(n_ * GPITCH + k_) * 2);
                rb[2 * a][0] = r0; rb[2 * a][1] = r1;
                rb[2 * a + 1][0] = r2; rb[2 * a + 1][1] = r3;
            }
            uint32_t ra[4][4];
#pragma unroll
            for (int mi = 0; mi < 4; mi++) {
                const int m_ = wm + mi * 16 + ((mat & 1) ? 8 : 0) + mrow;
                const int k_ = ks * 16 + ((mat >> 1) ? 8 : 0);
                ldsm4(ra[mi][0], ra[mi][1], ra[mi][2], ra[mi][3],
                      As_u + (uint32_t)(m_ * GPITCH + k_) * 2);
            }
#pragma unroll
            for (int mi = 0; mi < 4; mi++)
#pragma unroll
                for (int ni = 0; ni < 4; ni++)
                    mma_f16(acc[mi][ni], ra[mi][0], ra[mi][1], ra[mi][2], ra[mi][3],
                            rb[ni][0], rb[ni][1]);
        }
        __syncthreads();
    }

    // ---- epilogue ----
#pragma unroll
    for (int mi = 0; mi < 4; mi++) {
        const int row0 = bm + wm + mi * 16 + gr;
        const int row1 = row0 + 8;
#pragma unroll
        for (int ni = 0; ni < 4; ni++) {
            const int col = bn + wn + ni * 8 + 2 * tg;
            float v0 = acc[mi][ni][0], v1 = acc[mi][ni][1];
            float v2 = acc[mi][ni][2], v3 = acc[mi][ni][3];
            if (EPI == 1) {
                const float bb0 = bias[col], bb1 = bias[col + 1];
                v0 = gelu_exact(v0 + bb0); v1 = gelu_exact(v1 + bb1);
                v2 = gelu_exact(v2 + bb0); v3 = gelu_exact(v3 + bb1);
            }
            if (EPI == 2) {
                const float bb0 = bias[col], bb1 = bias[col + 1];
                const float2 r0 = *reinterpret_cast<const float2*>(&res[(size_t)row0 * N + col]);
                const float2 r1 = *reinterpret_cast<const float2*>(&res[(size_t)row1 * N + col]);
                v0 += bb0 + r0.x; v1 += bb1 + r0.y;
                v2 += bb0 + r1.x; v3 += bb1 + r1.y;
                *reinterpret_cast<float2*>(&Cf[(size_t)row0 * N + col]) = make_float2(v0, v1);
                *reinterpret_cast<float2*>(&Cf[(size_t)row1 * N + col]) = make_float2(v2, v3);
            } else {
                *reinterpret_cast<__half2*>(&Ch[(size_t)row0 * N + col]) =
                    __floats2half2_rn(v0, v1);
                *reinterpret_cast<__half2*>(&Ch[(size_t)row1 * N + col]) =
                    __floats2half2_rn(v2, v3);
            }
        }
    }
}

// ============ fp16 tensor-core causal flash attention ============
// 3-stage K/V cp.async, one barrier/iter, register-resident P, heavy-first,
// BASE-2 SOFTMAX: Q pre-scaled by (1/8)*log2(e); exp2f replaces __expf.
#define QPITCH 72
#define KPITCH 72
#define KV_STAGE (64 * KPITCH)          // halves per K (or V) stage
#define ATT_SMEM ((128*QPITCH + 3*KV_STAGE + 3*KV_STAGE) * 2)

__global__ void __launch_bounds__(256) attn_kernel(
    const __half* __restrict__ qkv, __half* __restrict__ O)
{
    const int qt = gridDim.x - 1 - blockIdx.x;   // heavy tiles scheduled first
    const int bh = blockIdx.y;
    const int bb = bh >> 4, hh = bh & 15;
    const int tid = threadIdx.x;
    const int lane = tid & 31, wid = tid >> 5;
    const int gr = lane >> 2, tg = lane & 3;
    const int mat = lane >> 3, mrow = lane & 7;
    const size_t rowbase = (size_t)bb * TSEQ;
    const int qoff = hh * DH;
    const int koff = DM + hh * DH;
    const int voff = 2 * DM + hh * DH;
    const int q0 = qt * 128;
    const int wr = wid * 16;

    extern __shared__ __half smh[];
    __half* Qs = smh;                           // [128][QPITCH]
    __half* Ks = Qs + 128 * QPITCH;             // 3 x [64][KPITCH]
    __half* Vs = Ks + 3 * KV_STAGE;             // 3 x [64][KPITCH]
    const uint32_t Qs_u = (uint32_t)__cvta_generic_to_shared(Qs);
    const uint32_t Ks_u = (uint32_t)__cvta_generic_to_shared(Ks);
    const uint32_t Vs_u = (uint32_t)__cvta_generic_to_shared(Vs);

    // load Q tile, pre-scaled by (1/8)*log2(e) -> S lives in log2 domain
    {
        const float qs = 0.125f * 1.4426950408889634f;
        const __half2 sc = __floats2half2_rn(qs, qs);
        for (int e = tid; e < 128 * 32; e += 256) {
            const int r = e >> 5, d2 = e & 31;
            __half2 v = *reinterpret_cast<const __half2*>(
                &qkv[(rowbase + q0 + r) * (size_t)(3 * DM) + qoff + 2 * d2]);
            *reinterpret_cast<__half2*>(&Qs[r * QPITCH + 2 * d2]) = __hmul2(v, sc);
        }
    }

    // async K/V stage loader (3-stage ring)
    auto issue_kv = [&](int kt) {
        const int s = kt % 3;
        const int k0 = kt * 64;
        __half* Kd = Ks + s * KV_STAGE;
        __half* Vd = Vs + s * KV_STAGE;
#pragma unroll
        for (int i = 0; i < 4; i++) {
            const int c = tid + i * 256;          // 0..1023
            const int sel = c >> 9;               // 0 = K, 1 = V
            const int r = (c >> 3) & 63;
            const int kc = (c & 7) * 8;
            const size_t base = (rowbase + k0 + r) * (size_t)(3 * DM);
            if (sel == 0) cp16(Kd + r * KPITCH + kc, qkv + base + koff + kc);
            else          cp16(Vd + r * KPITCH + kc, qkv + base + voff + kc);
        }
    };

    float oacc[8][4];
    float sacc[8][4];
    uint32_t pfrag[8][2];               // P as half2 fragments, register-resident
#pragma unroll
    for (int i = 0; i < 8; i++)
#pragma unroll
        for (int r = 0; r < 4; r++) oacc[i][r] = 0.f;
    float m0 = -1e30f, m1 = -1e30f, l0 = 0.f, l1 = 0.f;

    const int kt_max = 2 * qt + 1;
    issue_kv(0);
    asm volatile("cp.async.commit_group;\n");
    if (kt_max >= 1) { issue_kv(1); asm volatile("cp.async.commit_group;\n"); }

    for (int kt = 0; kt <= kt_max; kt++) {
        if (kt + 1 <= kt_max) asm volatile("cp.async.wait_group 1;\n");
        else                  asm volatile("cp.async.wait_group 0;\n");
        __syncthreads();   // stage kt visible; proves stage (kt-1)%3 reads finished
        if (kt + 2 <= kt_max) {
            issue_kv(kt + 2);
            asm volatile("cp.async.commit_group;\n");
        }

        const uint32_t Ksu = Ks_u + (uint32_t)((kt % 3) * KV_STAGE) * 2;
        const uint32_t Vsu = Vs_u + (uint32_t)((kt % 3) * KV_STAGE) * 2;
        const int k0 = kt * 64;

        // ---- S = Q K^T (log2 domain) ----
#pragma unroll
        for (int i = 0; i < 8; i++)
#pragma unroll
            for (int r = 0; r < 4; r++) sacc[i][r] = 0.f;
#pragma unroll
        for (int ks = 0; ks < 4; ks++) {
            uint32_t a0, a1, a2, a3;
            {
                const int m_ = wr + ((mat & 1) ? 8 : 0) + mrow;
                const int k_ = ks * 16 + ((mat >> 1) ? 8 : 0);
                ldsm4(a0, a1, a2, a3, Qs_u + (uint32_t)(m_ * QPITCH + k_) * 2);
            }
#pragma unroll
            for (int a = 0; a < 4; a++) {
                const int n_ = a * 16 + (mat >> 1) * 8 + mrow;
                const int d_ = ks * 16 + (mat & 1) * 8;
                uint32_t b0, b1, b2, b3;
                ldsm4(b0, b1, b2, b3, Ksu + (uint32_t)(n_ * KPITCH + d_) * 2);
                mma_f16(sacc[2 * a],     a0, a1, a2, a3, b0, b1);
                mma_f16(sacc[2 * a + 1], a0, a1, a2, a3, b2, b3);
            }
        }

        // ---- causal mask ----
        const int row_g0 = q0 + wr + gr, row_g1 = row_g0 + 8;
        if (kt >= 2 * qt) {
#pragma unroll
            for (int ni = 0; ni < 8; ni++) {
                const int c0 = k0 + ni * 8 + 2 * tg, c1 = c0 + 1;
                if (c0 > row_g0) sacc[ni][0] = -1e30f;
                if (c1 > row_g0) sacc[ni][1] = -1e30f;
                if (c0 > row_g1) sacc[ni][2] = -1e30f;
                if (c1 > row_g1) sacc[ni][3] = -1e30f;
            }
        }

        // ---- online softmax (base 2); P -> half2 register fragments ----
        float mx0 = -1e30f, mx1 = -1e30f;
#pragma unroll
        for (int ni = 0; ni < 8; ni++) {
            mx0 = fmaxf(mx0, fmaxf(sacc[ni][0], sacc[ni][1]));
            mx1 = fmaxf(mx1, fmaxf(sacc[ni][2], sacc[ni][3]));
        }
        mx0 = fmaxf(mx0, __shfl_xor_sync(0xffffffffu, mx0, 1));
        mx0 = fmaxf(mx0, __shfl_xor_sync(0xffffffffu, mx0, 2));
        mx1 = fmaxf(mx1, __shfl_xor_sync(0xffffffffu, mx1, 1));
        mx1 = fmaxf(mx1, __shfl_xor_sync(0xffffffffu, mx1, 2));
        const float mn0 = fmaxf(m0, mx0), mn1 = fmaxf(m1, mx1);
        const float al0 = exp2f(m0 - mn0), al1 = exp2f(m1 - mn1);
        float rs0 = 0.f, rs1 = 0.f;
#pragma unroll
        for (int ni = 0; ni < 8; ni++) {
            float p00 = exp2f(sacc[ni][0] - mn0);
            float p01 = exp2f(sacc[ni][1] - mn0);
            float p10 = exp2f(sacc[ni][2] - mn1);
            float p11 = exp2f(sacc[ni][3] - mn1);
            rs0 += p00 + p01; rs1 += p10 + p11;
            pfrag[ni][0] = h2u(__floats2half2_rn(p00, p01));   // row gr
            pfrag[ni][1] = h2u(__floats2half2_rn(p10, p11));   // row gr+8
        }
        rs0 += __shfl_xor_sync(0xffffffffu, rs0, 1);
        rs0 += __shfl_xor_sync(0xffffffffu, rs0, 2);
        rs1 += __shfl_xor_sync(0xffffffffu, rs1, 1);
        rs1 += __shfl_xor_sync(0xffffffffu, rs1, 2);
        l0 = l0 * al0 + rs0; l1 = l1 * al1 + rs1;
        m0 = mn0; m1 = mn1;
#pragma unroll
        for (int ni = 0; ni < 8; ni++) {
            oacc[ni][0] *= al0; oacc[ni][1] *= al0;
            oacc[ni][2] *= al1; oacc[ni][3] *= al1;
        }

        // ---- O += P V : A-fragments straight from registers ----
#pragma unroll
        for (int ks = 0; ks < 4; ks++) {
            const uint32_t a0 = pfrag[2 * ks][0];
            const uint32_t a1 = pfrag[2 * ks][1];
            const uint32_t a2 = pfrag[2 * ks + 1][0];
            const uint32_t a3 = pfrag[2 * ks + 1][1];
#pragma unroll
            for (int a = 0; a < 4; a++) {
                const int kk_ = ks * 16 + (mat & 1) * 8 + mrow;
                const int d_  = a * 16 + (mat >> 1) * 8;
                uint32_t b0, b1, b2, b3;
                ldsm4t(b0, b1, b2, b3, Vsu + (uint32_t)(kk_ * KPITCH + d_) * 2);
                mma_f16(oacc[2 * a],     a0, a1, a2, a3, b0, b1);
                mma_f16(oacc[2 * a + 1], a0, a1, a2, a3, b2, b3);
            }
        }
        // no trailing barrier: next iteration's barrier provides the ordering
    }

    // ---- write O (fp16) ----
    const float i0 = 1.0f / l0, i1 = 1.0f / l1;
    const size_t r0 = (rowbase + q0 + wr + gr) * (size_t)DM + hh * DH;
    const size_t r1 = r0 + 8 * DM;
#pragma unroll
    for (int ni = 0; ni < 8; ni++) {
        const int c = ni * 8 + 2 * tg;
        *reinterpret_cast<__half2*>(&O[r0 + c]) =
            __floats2half2_rn(oacc[ni][0] * i0, oacc[ni][1] * i0);
        *reinterpret_cast<__half2*>(&O[r1 + c]) =
            __floats2half2_rn(oacc[ni][2] * i1, oacc[ni][3] * i1);
    }
}

// ---------------- launcher ----------------
extern "C" void kernel_launch(void* const* d_in, const int* in_sizes, int n_in,
                              void* d_out, int out_size)
{
    const float* x     = (const float*)d_in[0];
    const float* ln1_g = (const float*)d_in[1];
    const float* ln1_b = (const float*)d_in[2];
    const float* w_qkv = (const float*)d_in[3];
    const float* w_out = (const float*)d_in[4];
    const float* b_out = (const float*)d_in[5];
    const float* ln2_g = (const float*)d_in[6];
    const float* ln2_b = (const float*)d_in[7];
    const float* w1    = (const float*)d_in[8];
    const float* b1    = (const float*)d_in[9];
    const float* w2    = (const float*)d_in[10];
    const float* b2    = (const float*)d_in[11];
    float* out = (float*)d_out;

    __half *h, *qkv, *o, *ff, *wc;
    float *x2;
    cudaGetSymbolAddress((void**)&h,   g_h);
    cudaGetSymbolAddress((void**)&qkv, g_qkv);
    cudaGetSymbolAddress((void**)&o,   g_o);
    cudaGetSymbolAddress((void**)&x2,  g_x2);
    cudaGetSymbolAddress((void**)&ff,  g_ff);
    cudaGetSymbolAddress((void**)&wc,  g_wc);

    __half* wqkv_t = wc;                       // [3072][1024]
    __half* wout_t = wqkv_t + DM * 3 * DM;     // [1024][1024]
    __half* w1_t   = wout_t + DM * DM;         // [4096][1024]
    __half* w2_t   = w1_t + DM * DFF;          // [1024][4096]

    cudaFuncSetAttribute(attn_kernel,
                         cudaFuncAttributeMaxDynamicSharedMemorySize, ATT_SMEM);
    cudaFuncSetAttribute(gemm_f16<0>,
                         cudaFuncAttributeMaxDynamicSharedMemorySize, GEMM_SMEM);
    cudaFuncSetAttribute(gemm_f16<1>,
                         cudaFuncAttributeMaxDynamicSharedMemorySize, GEMM_SMEM);
    cudaFuncSetAttribute(gemm_f16<2>,
                         cudaFuncAttributeMaxDynamicSharedMemorySize, GEMM_SMEM);

    // 0) all 4 weight transposes in ONE launch
    transpose_all_kernel<<<12288, dim3(32, 8)>>>(
        w_qkv, w_out, w1, w2, wqkv_t, wout_t, w1_t, w2_t);

    // 1) h = LN1(x)
    ln_kernel<<<NTOK, 256>>>(x, ln1_g, ln1_b, h);
    // 2) qkv = h @ w_qkv
    gemm_f16<0><<<dim3(3 * DM / 128, NTOK / 128), 256, GEMM_SMEM>>>(
        h, wqkv_t, nullptr, nullptr, nullptr, qkv, NTOK, 3 * DM, DM);
    // 3) o = causal_attention(qkv)
    attn_kernel<<<dim3(TSEQ / 128, 4 * NH), 256, ATT_SMEM>>>(qkv, o);
    // 4) x2 = x + o @ w_out + b_out  (fp32 out)
    gemm_f16<2><<<dim3(DM / 128, NTOK / 128), 256, GEMM_SMEM>>>(
        o, wout_t, b_out, x, x2, nullptr, NTOK, DM, DM);
    // 5) h = LN2(x2)
    ln_kernel<<<NTOK, 256>>>(x2, ln2_g, ln2_b, h);
    // 6) ff = gelu(h @ w1 + b1)
    gemm_f16<1><<<dim3(DFF / 128, NTOK / 128), 256, GEMM_SMEM>>>(
        h, w1_t, b1, nullptr, nullptr, ff, NTOK, DFF, DM);
    // 7) out = x2 + ff @ w2 + b2  (fp32 out)
    gemm_f16<2><<<dim3(DM / 128, NTOK / 128), 256, GEMM_SMEM>>>(
        ff, w2_t, b2, x2, out, nullptr, NTOK, DM, DFF);
}

// round 17
// speedup vs baseline: 1.1459x; 1.0454x over previous
#include <cuda_runtime.h>
#include <cuda_fp16.h>
#include <math.h>
#include <stdint.h>

#define NTOK   8192      // B*T
#define DM     1024
#define DFF    4096
#define TSEQ   2048
#define NH     16
#define DH     64

// ---------------- scratch (static device globals; no allocation) ----------------
__device__ __half g_h  [NTOK * DM];       // LN output (fp16)
__device__ __half g_qkv[NTOK * 3 * DM];   // qkv projections (fp16)
__device__ __half g_o  [NTOK * DM];       // attention output (fp16)
__device__ float  g_x2 [NTOK * DM];       // residual after attention (fp32)
__device__ __half g_ff [NTOK * DFF];      // gelu output (fp16)
__device__ __half g_wc [DM*3*DM + DM*DM + DM*DFF + DFF*DM]; // fp16 weights, [n][k]

// ---------------- fused weight transpose + fp16 convert (all 4 weights) ----------
__global__ void __launch_bounds__(256) transpose_all_kernel(
    const float* __restrict__ w0, const float* __restrict__ w1,
    const float* __restrict__ w2, const float* __restrict__ w3,
    __half* __restrict__ d0, __half* __restrict__ d1,
    __half* __restrict__ d2, __half* __restrict__ d3)
{
    __shared__ float tile[32][33];
    const int bid = blockIdx.x;
    const float* in; __half* out; int K, N, nx, local;
    if (bid < 3072)      { in = w0; out = d0; K = 1024; N = 3072; nx = 96;  local = bid; }
    else if (bid < 4096) { in = w1; out = d1; K = 1024; N = 1024; nx = 32;  local = bid - 3072; }
    else if (bid < 8192) { in = w2; out = d2; K = 1024; N = 4096; nx = 128; local = bid - 4096; }
    else                 { in = w3; out = d3; K = 4096; N = 1024; nx = 32;  local = bid - 8192; }
    const int n0 = (local % nx) * 32, k0 = (local / nx) * 32;
    const int tx = threadIdx.x, ty = threadIdx.y;   // block (32, 8)
#pragma unroll
    for (int i = 0; i < 4; i++)
        tile[ty + i * 8][tx] = in[(size_t)(k0 + ty + i * 8) * N + n0 + tx];
    __syncthreads();
#pragma unroll
    for (int i = 0; i < 4; i++)
        out[(size_t)(n0 + ty + i * 8) * K + k0 + tx] =
            __float2half_rn(tile[tx][ty + i * 8]);
}

// ---------------- LayerNorm: fp32 in -> fp16 out (vectorized) ----------------
__global__ void __launch_bounds__(256) ln_kernel(
    const float* __restrict__ x, const float* __restrict__ g,
    const float* __restrict__ b, __half* __restrict__ out)
{
    const int row = blockIdx.x;
    const int t4 = threadIdx.x * 4;
    const float4 v = *reinterpret_cast<const float4*>(x + (size_t)row * DM + t4);
    float s  = v.x + v.y + v.z + v.w;
    float s2 = v.x * v.x + v.y * v.y + v.z * v.z + v.w * v.w;
#pragma unroll
    for (int off = 16; off; off >>= 1) {
        s  += __shfl_xor_sync(0xffffffffu, s,  off);
        s2 += __shfl_xor_sync(0xffffffffu, s2, off);
    }
    __shared__ float ss[8], ss2[8];
    const int w = threadIdx.x >> 5, ln = threadIdx.x & 31;
    if (ln == 0) { ss[w] = s; ss2[w] = s2; }
    __syncthreads();
    s = 0.f; s2 = 0.f;
#pragma unroll
    for (int i = 0; i < 8; i++) { s += ss[i]; s2 += ss2[i]; }
    const float mean = s * (1.0f / DM);
    const float var  = s2 * (1.0f / DM) - mean * mean;
    const float rstd = rsqrtf(var + 1e-5f);
    const float4 gv = *reinterpret_cast<const float4*>(g + t4);
    const float4 bv = *reinterpret_cast<const float4*>(b + t4);
    __half2 h01 = __floats2half2_rn((v.x - mean) * rstd * gv.x + bv.x,
                                    (v.y - mean) * rstd * gv.y + bv.y);
    __half2 h23 = __floats2half2_rn((v.z - mean) * rstd * gv.z + bv.z,
                                    (v.w - mean) * rstd * gv.w + bv.w);
    __half2* orow = reinterpret_cast<__half2*>(out + (size_t)row * DM + t4);
    orow[0] = h01;
    orow[1] = h23;
}

// ================ fp16 tensor-core GEMM: BK=64, 2-stage, 128x128 ================
__device__ __forceinline__ float gelu_exact(float x) {
    return 0.5f * x * (1.0f + erff(x * 0.70710678118654752f));
}
__device__ __forceinline__ void ldsm4(uint32_t& r0, uint32_t& r1,
                                      uint32_t& r2, uint32_t& r3, uint32_t addr) {
    asm volatile("ldmatrix.sync.aligned.m8n8.x4.shared.b16 {%0,%1,%2,%3}, [%4];\n"
                 : "=r"(r0), "=r"(r1), "=r"(r2), "=r"(r3) : "r"(addr));
}
__device__ __forceinline__ void ldsm4t(uint32_t& r0, uint32_t& r1,
                                       uint32_t& r2, uint32_t& r3, uint32_t addr) {
    asm volatile("ldmatrix.sync.aligned.m8n8.x4.trans.shared.b16 {%0,%1,%2,%3}, [%4];\n"
                 : "=r"(r0), "=r"(r1), "=r"(r2), "=r"(r3) : "r"(addr));
}
__device__ __forceinline__ void mma_f16(float* c,
    uint32_t a0, uint32_t a1, uint32_t a2, uint32_t a3, uint32_t b0, uint32_t b1) {
    asm volatile(
        "mma.sync.aligned.m16n8k16.row.col.f32.f16.f16.f32 "
        "{%0,%1,%2,%3}, {%4,%5,%6,%7}, {%8,%9}, {%0,%1,%2,%3};\n"
        : "+f"(c[0]), "+f"(c[1]), "+f"(c[2]), "+f"(c[3])
        : "r"(a0), "r"(a1), "r"(a2), "r"(a3), "r"(b0), "r"(b1));
}
__device__ __forceinline__ void cp16(__half* dst, const __half* src) {
    uint32_t d = (uint32_t)__cvta_generic_to_shared(dst);
    asm volatile("cp.async.cg.shared.global [%0], [%1], 16;\n" :: "r"(d), "l"(src));
}
__device__ __forceinline__ uint32_t h2u(__half2 h) {
    uint32_t u;
    asm("mov.b32 %0, %1;" : "=r"(u) : "r"(*reinterpret_cast<uint32_t*>(&h)));
    return u;
}

#define GPITCH 72                       // halves per smem row (128B data + 16B pad)
#define G_TILE (128 * GPITCH)           // halves per operand tile (128 x 64)
#define G_STAGE (2 * G_TILE)            // halves per stage (A + B)
#define GEMM_SMEM (2 * G_STAGE * 2)     // bytes (= 73728), 2 stages

template<int EPI>
__global__ void __launch_bounds__(256) gemm_f16(
    const __half* __restrict__ A, const __half* __restrict__ Bt,
    const float* __restrict__ bias, const float* __restrict__ res,
    float* __restrict__ Cf, __half* __restrict__ Ch, int M, int N, int K)
{
    extern __shared__ __half smh[];
    const int tid  = threadIdx.x;
    const int lane = tid & 31, wid = tid >> 5;
    const int bm = blockIdx.y * 128, bn = blockIdx.x * 128;
    const int wm = (wid >> 2) * 64;
    const int wn = (wid & 3) * 32;
    const int gr = lane >> 2, tg = lane & 3;

    const uint32_t smem_u32 = (uint32_t)__cvta_generic_to_shared(smh);
    const int mat  = lane >> 3;
    const int mrow = lane & 7;

    float acc[4][4][4];
#pragma unroll
    for (int i = 0; i < 4; i++)
#pragma unroll
        for (int j = 0; j < 4; j++)
#pragma unroll
            for (int r = 0; r < 4; r++) acc[i][j][r] = 0.f;

    const int KT = K >> 6;   // K / 64

    auto issue = [&](int kt) {
        const int stg = kt & 1;
        const int k0 = kt << 6;
        __half* As = smh + stg * G_STAGE;
        __half* Bs = As + G_TILE;
#pragma unroll
        for (int i = 0; i < 4; i++) {
            const int c = tid + i * 256;             // 0..1023
            const int row = c >> 3, kc = (c & 7) * 8;
            cp16(As + row * GPITCH + kc, A  + (size_t)(bm + row) * K + k0 + kc);
        }
#pragma unroll
        for (int i = 0; i < 4; i++) {
            const int c = tid + i * 256;
            const int row = c >> 3, kc = (c & 7) * 8;
            cp16(Bs + row * GPITCH + kc, Bt + (size_t)(bn + row) * K + k0 + kc);
        }
    };

    issue(0);
    asm volatile("cp.async.commit_group;\n");

    for (int kt = 0; kt < KT; kt++) {
        if (kt + 1 < KT) {
            issue(kt + 1);
            asm volatile("cp.async.commit_group;\n");
            asm volatile("cp.async.wait_group 1;\n");
        } else {
            asm volatile("cp.async.wait_group 0;\n");
        }
        __syncthreads();

        const uint32_t As_u = smem_u32 + ((kt & 1) * G_STAGE) * 2;
        const uint32_t Bs_u = As_u + G_TILE * 2;

#pragma unroll
        for (int ks = 0; ks < 4; ks++) {
            uint32_t rb[4][2];
#pragma unroll
            for (int a = 0; a < 2; a++) {
                const int n_ = wn + a * 16 + (mat >> 1) * 8 + mrow;
                const int k_ = ks * 16 + (mat & 1) * 8;
                uint32_t r0, r1, r2, r3;
                ldsm4(r0, r1, r2, r3, Bs_u + (uint32_t)(n_ * GPITCH + k_) * 2);
                rb[2 * a][0] = r0; rb[2 * a][1] = r1;
                rb[2 * a + 1][0] = r2; rb[2 * a + 1][1] = r3;
            }
            uint32_t ra[4][4];
#pragma unroll
            for (int mi = 0; mi < 4; mi++) {
                const int m_ = wm + mi * 16 + ((mat & 1) ? 8 : 0) + mrow;
                const int k_ = ks * 16 + ((mat >> 1) ? 8 : 0);
                ldsm4(ra[mi][0], ra[mi][1], ra[mi][2], ra[mi][3],
                      As_u + (uint32_t)(m_ * GPITCH + k_) * 2);
            }
#pragma unroll
            for (int mi = 0; mi < 4; mi++)
#pragma unroll
                for (int ni = 0; ni < 4; ni++)
                    mma_f16(acc[mi][ni], ra[mi][0], ra[mi][1], ra[mi][2], ra[mi][3],
                            rb[ni][0], rb[ni][1]);
        }
        __syncthreads();
    }

    // ---- epilogue ----
#pragma unroll
    for (int mi = 0; mi < 4; mi++) {
        const int row0 = bm + wm + mi * 16 + gr;
        const int row1 = row0 + 8;
#pragma unroll
        for (int ni = 0; ni < 4; ni++) {
            const int col = bn + wn + ni * 8 + 2 * tg;
            float v0 = acc[mi][ni][0], v1 = acc[mi][ni][1];
            float v2 = acc[mi][ni][2], v3 = acc[mi][ni][3];
            if (EPI == 1) {
                const float bb0 = bias[col], bb1 = bias[col + 1];
                v0 = gelu_exact(v0 + bb0); v1 = gelu_exact(v1 + bb1);
                v2 = gelu_exact(v2 + bb0); v3 = gelu_exact(v3 + bb1);
            }
            if (EPI == 2) {
                const float bb0 = bias[col], bb1 = bias[col + 1];
                const float2 r0 = *reinterpret_cast<const float2*>(&res[(size_t)row0 * N + col]);
                const float2 r1 = *reinterpret_cast<const float2*>(&res[(size_t)row1 * N + col]);
                v0 += bb0 + r0.x; v1 += bb1 + r0.y;
                v2 += bb0 + r1.x; v3 += bb1 + r1.y;
                *reinterpret_cast<float2*>(&Cf[(size_t)row0 * N + col]) = make_float2(v0, v1);
                *reinterpret_cast<float2*>(&Cf[(size_t)row1 * N + col]) = make_float2(v2, v3);
            } else {
                *reinterpret_cast<__half2*>(&Ch[(size_t)row0 * N + col]) =
                    __floats2half2_rn(v0, v1);
                *reinterpret_cast<__half2*>(&Ch[(size_t)row1 * N + col]) =
                    __floats2half2_rn(v2, v3);
            }
        }
    }
}

// ============ fp16 tensor-core causal flash attention (R16-exact) ============
#define QPITCH 72
#define KPITCH 72
#define KV_STAGE (64 * KPITCH)          // halves per K (or V) stage
#define ATT_SMEM ((128*QPITCH + 3*KV_STAGE + 3*KV_STAGE) * 2)

__global__ void __launch_bounds__(256) attn_kernel(
    const __half* __restrict__ qkv, __half* __restrict__ O)
{
    const int qt = gridDim.x - 1 - blockIdx.x;   // heavy tiles scheduled first
    const int bh = blockIdx.y;
    const int bb = bh >> 4, hh = bh & 15;
    const int tid = threadIdx.x;
    const int lane = tid & 31, wid = tid >> 5;
    const int gr = lane >> 2, tg = lane & 3;
    const int mat = lane >> 3, mrow = lane & 7;
    const size_t rowbase = (size_t)bb * TSEQ;
    const int qoff = hh * DH;
    const int koff = DM + hh * DH;
    const int voff = 2 * DM + hh * DH;
    const int q0 = qt * 128;
    const int wr = wid * 16;

    extern __shared__ __half smh[];
    __half* Qs = smh;                           // [128][QPITCH]
    __half* Ks = Qs + 128 * QPITCH;             // 3 x [64][KPITCH]
    __half* Vs = Ks + 3 * KV_STAGE;             // 3 x [64][KPITCH]
    const uint32_t Qs_u = (uint32_t)__cvta_generic_to_shared(Qs);
    const uint32_t Ks_u = (uint32_t)__cvta_generic_to_shared(Ks);
    const uint32_t Vs_u = (uint32_t)__cvta_generic_to_shared(Vs);

    // load Q tile, pre-scaled by (1/8)*log2(e) -> S lives in log2 domain
    {
        const float qs = 0.125f * 1.4426950408889634f;
        const __half2 sc = __floats2half2_rn(qs, qs);
        for (int e = tid; e < 128 * 32; e += 256) {
            const int r = e >> 5, d2 = e & 31;
            __half2 v = *reinterpret_cast<const __half2*>(
                &qkv[(rowbase + q0 + r) * (size_t)(3 * DM) + qoff + 2 * d2]);
            *reinterpret_cast<__half2*>(&Qs[r * QPITCH + 2 * d2]) = __hmul2(v, sc);
        }
    }

    // async K/V stage loader (3-stage ring)
    auto issue_kv = [&](int kt) {
        const int s = kt % 3;
        const int k0 = kt * 64;
        __half* Kd = Ks + s * KV_STAGE;
        __half* Vd = Vs + s * KV_STAGE;
#pragma unroll
        for (int i = 0; i < 4; i++) {
            const int c = tid + i * 256;          // 0..1023
            const int sel = c >> 9;               // 0 = K, 1 = V
            const int r = (c >> 3) & 63;
            const int kc = (c & 7) * 8;
            const size_t base = (rowbase + k0 + r) * (size_t)(3 * DM);
            if (sel == 0) cp16(Kd + r * KPITCH + kc, qkv + base + koff + kc);
            else          cp16(Vd + r * KPITCH + kc, qkv + base + voff + kc);
        }
    };

    float oacc[8][4];
    float sacc[8][4];
    uint32_t pfrag[8][2];               // P as half2 fragments, register-resident
#pragma unroll
    for (int i = 0; i < 8; i++)
#pragma unroll
        for (int r = 0; r < 4; r++) oacc[i][r] = 0.f;
    float m0 = -1e30f, m1 = -1e30f, l0 = 0.f, l1 = 0.f;

    const int kt_max = 2 * qt + 1;
    issue_kv(0);
    asm volatile("cp.async.commit_group;\n");
    if (kt_max >= 1) { issue_kv(1); asm volatile("cp.async.commit_group;\n"); }

    for (int kt = 0; kt <= kt_max; kt++) {
        if (kt + 1 <= kt_max) asm volatile("cp.async.wait_group 1;\n");
        else                  asm volatile("cp.async.wait_group 0;\n");
        __syncthreads();   // stage kt visible; proves stage (kt-1)%3 reads finished
        if (kt + 2 <= kt_max) {
            issue_kv(kt + 2);
            asm volatile("cp.async.commit_group;\n");
        }

        const uint32_t Ksu = Ks_u + (uint32_t)((kt % 3) * KV_STAGE) * 2;
        const uint32_t Vsu = Vs_u + (uint32_t)((kt % 3) * KV_STAGE) * 2;
        const int k0 = kt * 64;

        // ---- S = Q K^T (log2 domain) ----
#pragma unroll
        for (int i = 0; i < 8; i++)
#pragma unroll
            for (int r = 0; r < 4; r++) sacc[i][r] = 0.f;
#pragma unroll
        for (int ks = 0; ks < 4; ks++) {
            uint32_t a0, a1, a2, a3;
            {
                const int m_ = wr + ((mat & 1) ? 8 : 0) + mrow;
                const int k_ = ks * 16 + ((mat >> 1) ? 8 : 0);
                ldsm4(a0, a1, a2, a3, Qs_u + (uint32_t)(m_ * QPITCH + k_) * 2);
            }
#pragma unroll
            for (int a = 0; a < 4; a++) {
                const int n_ = a * 16 + (mat >> 1) * 8 + mrow;
                const int d_ = ks * 16 + (mat & 1) * 8;
                uint32_t b0, b1, b2, b3;
                ldsm4(b0, b1, b2, b3, Ksu + (uint32_t)(n_ * KPITCH + d_) * 2);
                mma_f16(sacc[2 * a],     a0, a1, a2, a3, b0, b1);
                mma_f16(sacc[2 * a + 1], a0, a1, a2, a3, b2, b3);
            }
        }

        // ---- causal mask ----
        const int row_g0 = q0 + wr + gr, row_g1 = row_g0 + 8;
        if (kt >= 2 * qt) {
#pragma unroll
            for (int ni = 0; ni < 8; ni++) {
                const int c0 = k0 + ni * 8 + 2 * tg, c1 = c0 + 1;
                if (c0 > row_g0) sacc[ni][0] = -1e30f;
                if (c1 > row_g0) sacc[ni][1] = -1e30f;
                if (c0 > row_g1) sacc[ni][2] = -1e30f;
                if (c1 > row_g1) sacc[ni][3] = -1e30f;
            }
        }

        // ---- online softmax (base 2); P -> half2 register fragments ----
        float mx0 = -1e30f, mx1 = -1e30f;
#pragma unroll
        for (int ni = 0; ni < 8; ni++) {
            mx0 = fmaxf(mx0, fmaxf(sacc[ni][0], sacc[ni][1]));
            mx1 = fmaxf(mx1, fmaxf(sacc[ni][2], sacc[ni][3]));
        }
        mx0 = fmaxf(mx0, __shfl_xor_sync(0xffffffffu, mx0, 1));
        mx0 = fmaxf(mx0, __shfl_xor_sync(0xffffffffu, mx0, 2));
        mx1 = fmaxf(mx1, __shfl_xor_sync(0xffffffffu, mx1, 1));
        mx1 = fmaxf(mx1, __shfl_xor_sync(0xffffffffu, mx1, 2));
        const float mn0 = fmaxf(m0, mx0), mn1 = fmaxf(m1, mx1);
        const float al0 = exp2f(m0 - mn0), al1 = exp2f(m1 - mn1);
        float rs0 = 0.f, rs1 = 0.f;
#pragma unroll
        for (int ni = 0; ni < 8; ni++) {
            float p00 = exp2f(sacc[ni][0] - mn0);
            float p01 = exp2f(sacc[ni][1] - mn0);
            float p10 = exp2f(sacc[ni][2] - mn1);
            float p11 = exp2f(sacc[ni][3] - mn1);
            rs0 += p00 + p01; rs1 += p10 + p11;
            pfrag[ni][0] = h2u(__floats2half2_rn(p00, p01));   // row gr
            pfrag[ni][1] = h2u(__floats2half2_rn(p10, p11));   // row gr+8
        }
        rs0 += __shfl_xor_sync(0xffffffffu, rs0, 1);
        rs0 += __shfl_xor_sync(0xffffffffu, rs0, 2);
        rs1 += __shfl_xor_sync(0xffffffffu, rs1, 1);
        rs1 += __shfl_xor_sync(0xffffffffu, rs1, 2);
        l0 = l0 * al0 + rs0; l1 = l1 * al1 + rs1;
        m0 = mn0; m1 = mn1;
#pragma unroll
        for (int ni = 0; ni < 8; ni++) {
            oacc[ni][0] *= al0; oacc[ni][1] *= al0;
            oacc[ni][2] *= al1; oacc[ni][3] *= al1;
        }

        // ---- O += P V : A-fragments straight from registers ----
#pragma unroll
        for (int ks = 0; ks < 4; ks++) {
            const uint32_t a0 = pfrag[2 * ks][0];
            const uint32_t a1 = pfrag[2 * ks][1];
            const uint32_t a2 = pfrag[2 * ks + 1][0];
            const uint32_t a3 = pfrag[2 * ks + 1][1];
#pragma unroll
            for (int a = 0; a < 4; a++) {
                const int kk_ = ks * 16 + (mat & 1) * 8 + mrow;
                const int d_  = a * 16 + (mat >> 1) * 8;
                uint32_t b0, b1, b2, b3;
                ldsm4t(b0, b1, b2, b3, Vsu + (uint32_t)(kk_ * KPITCH + d_) * 2);
                mma_f16(oacc[2 * a],     a0, a1, a2, a3, b0, b1);
                mma_f16(oacc[2 * a + 1], a0, a1, a2, a3, b2, b3);
            }
        }
        // no trailing barrier: next iteration's barrier provides the ordering
    }

    // ---- write O (fp16) ----
    const float i0 = 1.0f / l0, i1 = 1.0f / l1;
    const size_t r0 = (rowbase + q0 + wr + gr) * (size_t)DM + hh * DH;
    const size_t r1 = r0 + 8 * DM;
#pragma unroll
    for (int ni = 0; ni < 8; ni++) {
        const int c = ni * 8 + 2 * tg;
        *reinterpret_cast<__half2*>(&O[r0 + c]) =
            __floats2half2_rn(oacc[ni][0] * i0, oacc[ni][1] * i0);
        *reinterpret_cast<__half2*>(&O[r1 + c]) =
            __floats2half2_rn(oacc[ni][2] * i1, oacc[ni][3] * i1);
    }
}

// ---------------- launcher ----------------
extern "C" void kernel_launch(void* const* d_in, const int* in_sizes, int n_in,
                              void* d_out, int out_size)
{
    const float* x     = (const float*)d_in[0];
    const float* ln1_g = (const float*)d_in[1];
    const float* ln1_b = (const float*)d_in[2];
    const float* w_qkv = (const float*)d_in[3];
    const float* w_out = (const float*)d_in[4];
    const float* b_out = (const float*)d_in[5];
    const float* ln2_g = (const float*)d_in[6];
    const float* ln2_b = (const float*)d_in[7];
    const float* w1    = (const float*)d_in[8];
    const float* b1    = (const float*)d_in[9];
    const float* w2    = (const float*)d_in[10];
    const float* b2    = (const float*)d_in[11];
    float* out = (float*)d_out;

    __half *h, *qkv, *o, *ff, *wc;
    float *x2;
    cudaGetSymbolAddress((void**)&h,   g_h);
    cudaGetSymbolAddress((void**)&qkv, g_qkv);
    cudaGetSymbolAddress((void**)&o,   g_o);
    cudaGetSymbolAddress((void**)&x2,  g_x2);
    cudaGetSymbolAddress((void**)&ff,  g_ff);
    cudaGetSymbolAddress((void**)&wc,  g_wc);

    __half* wqkv_t = wc;                       // [3072][1024]
    __half* wout_t = wqkv_t + DM * 3 * DM;     // [1024][1024]
    __half* w1_t   = wout_t + DM * DM;         // [4096][1024]
    __half* w2_t   = w1_t + DM * DFF;          // [1024][4096]

    cudaFuncSetAttribute(attn_kernel,
                         cudaFuncAttributeMaxDynamicSharedMemorySize, ATT_SMEM);
    cudaFuncSetAttribute(gemm_f16<0>,
                         cudaFuncAttributeMaxDynamicSharedMemorySize, GEMM_SMEM);
    cudaFuncSetAttribute(gemm_f16<1>,
                         cudaFuncAttributeMaxDynamicSharedMemorySize, GEMM_SMEM);
    cudaFuncSetAttribute(gemm_f16<2>,
                         cudaFuncAttributeMaxDynamicSharedMemorySize, GEMM_SMEM);

    // 0) all 4 weight transposes in ONE launch
    transpose_all_kernel<<<12288, dim3(32, 8)>>>(
        w_qkv, w_out, w1, w2, wqkv_t, wout_t, w1_t, w2_t);

    // 1) h = LN1(x)
    ln_kernel<<<NTOK, 256>>>(x, ln1_g, ln1_b, h);
    // 2) qkv = h @ w_qkv
    gemm_f16<0><<<dim3(3 * DM / 128, NTOK / 128), 256, GEMM_SMEM>>>(
        h, wqkv_t, nullptr, nullptr, nullptr, qkv, NTOK, 3 * DM, DM);
    // 3) o = causal_attention(qkv)
    attn_kernel<<<dim3(TSEQ / 128, 4 * NH), 256, ATT_SMEM>>>(qkv, o);
    // 4) x2 = x + o @ w_out + b_out  (fp32 out)
    gemm_f16<2><<<dim3(DM / 128, NTOK / 128), 256, GEMM_SMEM>>>(
        o, wout_t, b_out, x, x2, nullptr, NTOK, DM, DM);
    // 5) h = LN2(x2)
    ln_kernel<<<NTOK, 256>>>(x2, ln2_g, ln2_b, h);
    // 6) ff = gelu(h @ w1 + b1)
    gemm_f16<1><<<dim3(DFF / 128, NTOK / 128), 256, GEMM_SMEM>>>(
        h, w1_t, b1, nullptr, nullptr, ff, NTOK, DFF, DM);
    // 7) out = x2 + ff @ w2 + b2  (fp32 out)
    gemm_f16<2><<<dim3(DM / 128, NTOK / 128), 256, GEMM_SMEM>>>(
        ff, w2_t, b2, x2, out, nullptr, NTOK, DM, DFF);
}